// round 3
// baseline (speedup 1.0000x reference)
#include <cuda_runtime.h>
#include <math.h>

// Post_rois: SSD post-processing (softmax scores + box decode + greedy NMS + top-200)
// Inputs: loc [8,4096,4] f32, conf [8*4096,2] f32, prior [4096,4] f32 (cx,cy,w,h)
// Output: f32 [8, 2, 200, 5]; class-0 slice zeros, class-1 = NMS rows [s,x1,y1,x2,y2].

#define BATCH    8
#define NPRI     4096
#define TOPK     200
#define BLK      512      // 8 elements per thread
#define EPT      8
#define CONF_TH  0.01f
#define NMS_TH   0.45f

// dynamic smem: uint64 spk[4096] (32KB) + float4 sbox[4096] (64KB) + float sarea[4096] (16KB)
#define SMEM_BYTES (NPRI * (8 + 16 + 4))

typedef unsigned long long u64;

// compare-exchange: a is the LOWER-index element. desc=true -> a gets the max.
__device__ __forceinline__ void ce(u64 &a, u64 &b, bool desc) {
    u64 lo = a < b ? a : b;
    u64 hi = a < b ? b : a;
    a = desc ? hi : lo;
    b = desc ? lo : hi;
}

// full local merge of an 8-element bitonic sequence, uniform direction
__device__ __forceinline__ void local_merge8(u64 v[EPT], bool d) {
    ce(v[0],v[4],d); ce(v[1],v[5],d); ce(v[2],v[6],d); ce(v[3],v[7],d);
    ce(v[0],v[2],d); ce(v[1],v[3],d); ce(v[4],v[6],d); ce(v[5],v[7],d);
    ce(v[0],v[1],d); ce(v[2],v[3],d); ce(v[4],v[5],d); ce(v[6],v[7],d);
}

// phases k=2,4,8 within one thread's 8 contiguous elements (i = 8*tid + r)
__device__ __forceinline__ void local_sort8(u64 v[EPT], bool dir8) {
    // k=2 (dir = ((i&2)==0))
    ce(v[0],v[1],true);  ce(v[2],v[3],false); ce(v[4],v[5],true);  ce(v[6],v[7],false);
    // k=4, j=2 (dir = ((i&4)==0))
    ce(v[0],v[2],true);  ce(v[1],v[3],true);  ce(v[4],v[6],false); ce(v[5],v[7],false);
    // k=4, j=1
    ce(v[0],v[1],true);  ce(v[2],v[3],true);  ce(v[4],v[5],false); ce(v[6],v[7],false);
    // k=8 (dir uniform per thread)
    local_merge8(v, dir8);
}

// cross-thread (within-warp) stage j = 8*d via shfl.xor; dir uniform per warp here
__device__ __forceinline__ void shfl_stage(u64 v[EPT], int d, bool dirT, int tid) {
    bool keep_max = (((tid & d) == 0) == dirT);
    #pragma unroll
    for (int r = 0; r < EPT; r++) {
        u64 o = __shfl_xor_sync(0xffffffffu, v[r], d);
        v[r] = keep_max ? (v[r] > o ? v[r] : o) : (v[r] < o ? v[r] : o);
    }
}

__global__ __launch_bounds__(BLK, 1)
void post_rois_kernel(const float* __restrict__ loc,
                      const float* __restrict__ conf,
                      const float* __restrict__ prior,
                      float* __restrict__ out)
{
    const int b   = blockIdx.x;
    const int tid = threadIdx.x;

    extern __shared__ unsigned char smem_raw[];
    u64*    spk   = (u64*)smem_raw;                 // packed (score, idx), sorted desc
    float4* sbox  = (float4*)(spk + NPRI);          // decoded boxes in sorted order
    float*  sarea = (float*)(sbox + NPRI);

    // ---- zero this image's output slice ----
    float* ob = out + (size_t)b * 2 * TOPK * 5;
    for (int i = tid; i < 2 * TOPK * 5; i += BLK) ob[i] = 0.0f;

    // ---- phase 1: softmax scores, pack into sortable u64 ----
    // desc order on packed == (-score asc, idx asc) == reference stable argsort(-scores)
    for (int n = tid; n < NPRI; n += BLK) {
        float c0 = conf[((size_t)b * NPRI + n) * 2 + 0];
        float c1 = conf[((size_t)b * NPRI + n) * 2 + 1];
        float m  = fmaxf(c0, c1);
        float e0 = expf(__fsub_rn(c0, m));
        float e1 = expf(__fsub_rn(c1, m));
        float s  = __fdiv_rn(e1, __fadd_rn(e0, e1));   // in (0,1): positive, bits monotone
        spk[n] = ((u64)__float_as_uint(s) << 32) | (unsigned)(NPRI - 1 - n);
    }
    __syncthreads();

    // ---- phase 2: bitonic sort (descending), 8 elems/thread in registers ----
    u64 v[EPT];
    #pragma unroll
    for (int r = 0; r < EPT; r++) v[r] = spk[tid * EPT + r];

    local_sort8(v, (tid & 1) == 0);                       // k = 2,4,8

    for (int k = 16; k <= 256; k <<= 1) {                 // fully warp-local, 0 barriers
        bool dirT = ((tid & (k >> 3)) == 0);
        for (int d = (k >> 4); d >= 1; d >>= 1) shfl_stage(v, d, dirT, tid);
        local_merge8(v, dirT);
    }

    for (int k = 512; k <= (int)NPRI; k <<= 1) {          // cross-warp phases
        #pragma unroll
        for (int r = 0; r < EPT; r++) spk[tid * EPT + r] = v[r];
        __syncthreads();
        for (int j = (k >> 1); j >= 256; j >>= 1) {       // smem stages
            for (int m = tid; m < NPRI / 2; m += BLK) {
                int i = ((m & ~(j - 1)) << 1) | (m & (j - 1));
                int p = i | j;
                u64 a = spk[i], c = spk[p];
                bool desc = ((i & k) == 0);
                if (desc ? (a < c) : (a > c)) { spk[i] = c; spk[p] = a; }
            }
            __syncthreads();
        }
        #pragma unroll
        for (int r = 0; r < EPT; r++) v[r] = spk[tid * EPT + r];
        bool dirT = ((tid & (k >> 3)) == 0);
        for (int d = 16; d >= 1; d >>= 1) shfl_stage(v, d, dirT, tid);
        local_merge8(v, dirT);
    }

    #pragma unroll
    for (int r = 0; r < EPT; r++) spk[tid * EPT + r] = v[r];
    __syncthreads();

    // ---- phase 3: decode boxes into sorted order (pinned IEEE, no FMA) ----
    for (int p = tid; p < NPRI; p += BLK) {
        int n = NPRI - 1 - (int)(unsigned)(spk[p] & 0xffffffffu);
        const float* lp = loc + ((size_t)b * NPRI + n) * 4;
        float lx = lp[0], ly = lp[1], lw = lp[2], lh = lp[3];
        float pcx = prior[n * 4 + 0], pcy = prior[n * 4 + 1];
        float pw  = prior[n * 4 + 2], ph  = prior[n * 4 + 3];

        float cx = __fadd_rn(pcx, __fmul_rn(__fmul_rn(lx, 0.1f), pw));
        float cy = __fadd_rn(pcy, __fmul_rn(__fmul_rn(ly, 0.1f), ph));
        float w  = __fmul_rn(pw, expf(__fmul_rn(lw, 0.2f)));
        float h  = __fmul_rn(ph, expf(__fmul_rn(lh, 0.2f)));
        float hw = __fmul_rn(w, 0.5f);
        float hh = __fmul_rn(h, 0.5f);
        float x1 = __fsub_rn(cx, hw), y1 = __fsub_rn(cy, hh);
        float x2 = __fadd_rn(cx, hw), y2 = __fadd_rn(cy, hh);

        sbox[p]  = make_float4(x1, y1, x2, y2);
        sarea[p] = __fmul_rn(__fsub_rn(x2, x1), __fsub_rn(y2, y1));
    }
    __syncthreads();

    // ---- phase 4: greedy NMS, single warp, kept set in registers ----
    // kept box k lives at lane (k & 31), register slot (k >> 5); kept < 200 -> <= 7 slots
    if (tid < 32) {
        float4 kb[7];
        float  ka[7];
        int kept = 0;

        for (int i = 0; i < NPRI && kept < TOPK; i++) {
            u64 pk  = spk[i];                                   // smem broadcast
            float s = __uint_as_float((unsigned)(pk >> 32));
            if (!(s > CONF_TH)) break;                          // sorted desc

            float4 bi = sbox[i];
            float  ai = sarea[i];

            bool sup = false;
            #pragma unroll
            for (int r = 0; r < 7; r++) {
                if ((r << 5) + tid < kept) {
                    float iw = fmaxf(__fsub_rn(fminf(bi.z, kb[r].z), fmaxf(bi.x, kb[r].x)), 0.0f);
                    float ih = fmaxf(__fsub_rn(fminf(bi.w, kb[r].w), fmaxf(bi.y, kb[r].y)), 0.0f);
                    float inter = __fmul_rn(iw, ih);
                    float denom = __fsub_rn(__fadd_rn(ka[r], ai), inter);
                    sup |= (__fdiv_rn(inter, denom) > NMS_TH);
                }
            }
            if (__any_sync(0xffffffffu, sup)) continue;

            #pragma unroll
            for (int r = 0; r < 7; r++) {
                if ((kept >> 5) == r && (kept & 31) == tid) { kb[r] = bi; ka[r] = ai; }
            }
            if (tid == 0) {
                float* row = ob + (size_t)(TOPK + kept) * 5;    // class-1 slice
                row[0] = s;
                row[1] = bi.x; row[2] = bi.y; row[3] = bi.z; row[4] = bi.w;
            }
            kept++;
        }
    }
}

extern "C" void kernel_launch(void* const* d_in, const int* in_sizes, int n_in,
                              void* d_out, int out_size)
{
    const float* loc   = (const float*)d_in[0];
    const float* conf  = (const float*)d_in[1];
    const float* prior = (const float*)d_in[2];
    float* out = (float*)d_out;

    cudaFuncSetAttribute(post_rois_kernel,
                         cudaFuncAttributeMaxDynamicSharedMemorySize, SMEM_BYTES);
    post_rois_kernel<<<BATCH, BLK, SMEM_BYTES>>>(loc, conf, prior, out);
}

// round 4
// speedup vs baseline: 1.0007x; 1.0007x over previous
#include <cuda_runtime.h>
#include <math.h>

// Post_rois: SSD post-processing (softmax scores + box decode + greedy NMS + top-200)
// Inputs: loc [8,4096,4] f32, conf [8*4096,2] f32, prior [4096,4] f32 (cx,cy,w,h)
// Output: f32 [8, 2, 200, 5]; class-0 slice zeros, class-1 = NMS rows [s,x1,y1,x2,y2].

#define BATCH    8
#define NPRI     4096
#define TOPK     200
#define BLK      512      // 8 elements per thread
#define EPT      8
#define CONF_TH  0.01f
#define NMS_TH   0.45f

// dynamic smem: uint64 spk[4096] (32KB) + float4 sbox[4096] (64KB) + float sarea[4096] (16KB)
#define SMEM_BYTES (NPRI * (8 + 16 + 4))

typedef unsigned long long u64;

// compare-exchange: a is the LOWER-index element. desc=true -> a gets the max.
__device__ __forceinline__ void ce(u64 &a, u64 &b, bool desc) {
    u64 lo = a < b ? a : b;
    u64 hi = a < b ? b : a;
    a = desc ? hi : lo;
    b = desc ? lo : hi;
}

// full local merge of an 8-element bitonic sequence, uniform direction
__device__ __forceinline__ void local_merge8(u64 v[EPT], bool d) {
    ce(v[0],v[4],d); ce(v[1],v[5],d); ce(v[2],v[6],d); ce(v[3],v[7],d);
    ce(v[0],v[2],d); ce(v[1],v[3],d); ce(v[4],v[6],d); ce(v[5],v[7],d);
    ce(v[0],v[1],d); ce(v[2],v[3],d); ce(v[4],v[5],d); ce(v[6],v[7],d);
}

// phases k=2,4,8 within one thread's 8 contiguous elements (i = 8*tid + r)
__device__ __forceinline__ void local_sort8(u64 v[EPT], bool dir8) {
    // k=2 (dir = ((i&2)==0))
    ce(v[0],v[1],true);  ce(v[2],v[3],false); ce(v[4],v[5],true);  ce(v[6],v[7],false);
    // k=4, j=2 (dir = ((i&4)==0))
    ce(v[0],v[2],true);  ce(v[1],v[3],true);  ce(v[4],v[6],false); ce(v[5],v[7],false);
    // k=4, j=1
    ce(v[0],v[1],true);  ce(v[2],v[3],true);  ce(v[4],v[5],false); ce(v[6],v[7],false);
    // k=8 (dir uniform per thread)
    local_merge8(v, dir8);
}

// cross-thread (within-warp) stage j = 8*d via shfl.xor; dir uniform per warp here
__device__ __forceinline__ void shfl_stage(u64 v[EPT], int d, bool dirT, int tid) {
    bool keep_max = (((tid & d) == 0) == dirT);
    #pragma unroll
    for (int r = 0; r < EPT; r++) {
        u64 o = __shfl_xor_sync(0xffffffffu, v[r], d);
        v[r] = keep_max ? (v[r] > o ? v[r] : o) : (v[r] < o ? v[r] : o);
    }
}

__global__ __launch_bounds__(BLK, 1)
void post_rois_kernel(const float* __restrict__ loc,
                      const float* __restrict__ conf,
                      const float* __restrict__ prior,
                      float* __restrict__ out)
{
    const int b   = blockIdx.x;
    const int tid = threadIdx.x;

    extern __shared__ unsigned char smem_raw[];
    u64*    spk   = (u64*)smem_raw;                 // packed (score, idx), sorted desc
    float4* sbox  = (float4*)(spk + NPRI);          // decoded boxes in sorted order
    float*  sarea = (float*)(sbox + NPRI);

    // ---- zero this image's output slice ----
    float* ob = out + (size_t)b * 2 * TOPK * 5;
    for (int i = tid; i < 2 * TOPK * 5; i += BLK) ob[i] = 0.0f;

    // ---- phase 1: softmax scores, pack into sortable u64 ----
    // desc order on packed == (-score asc, idx asc) == reference stable argsort(-scores)
    for (int n = tid; n < NPRI; n += BLK) {
        float c0 = conf[((size_t)b * NPRI + n) * 2 + 0];
        float c1 = conf[((size_t)b * NPRI + n) * 2 + 1];
        float m  = fmaxf(c0, c1);
        float e0 = expf(__fsub_rn(c0, m));
        float e1 = expf(__fsub_rn(c1, m));
        float s  = __fdiv_rn(e1, __fadd_rn(e0, e1));   // in (0,1): positive, bits monotone
        spk[n] = ((u64)__float_as_uint(s) << 32) | (unsigned)(NPRI - 1 - n);
    }
    __syncthreads();

    // ---- phase 2: bitonic sort (descending), 8 elems/thread in registers ----
    u64 v[EPT];
    #pragma unroll
    for (int r = 0; r < EPT; r++) v[r] = spk[tid * EPT + r];

    local_sort8(v, (tid & 1) == 0);                       // k = 2,4,8

    for (int k = 16; k <= 256; k <<= 1) {                 // fully warp-local, 0 barriers
        bool dirT = ((tid & (k >> 3)) == 0);
        for (int d = (k >> 4); d >= 1; d >>= 1) shfl_stage(v, d, dirT, tid);
        local_merge8(v, dirT);
    }

    for (int k = 512; k <= (int)NPRI; k <<= 1) {          // cross-warp phases
        #pragma unroll
        for (int r = 0; r < EPT; r++) spk[tid * EPT + r] = v[r];
        __syncthreads();
        for (int j = (k >> 1); j >= 256; j >>= 1) {       // smem stages
            for (int m = tid; m < NPRI / 2; m += BLK) {
                int i = ((m & ~(j - 1)) << 1) | (m & (j - 1));
                int p = i | j;
                u64 a = spk[i], c = spk[p];
                bool desc = ((i & k) == 0);
                if (desc ? (a < c) : (a > c)) { spk[i] = c; spk[p] = a; }
            }
            __syncthreads();
        }
        #pragma unroll
        for (int r = 0; r < EPT; r++) v[r] = spk[tid * EPT + r];
        bool dirT = ((tid & (k >> 3)) == 0);
        for (int d = 16; d >= 1; d >>= 1) shfl_stage(v, d, dirT, tid);
        local_merge8(v, dirT);
    }

    #pragma unroll
    for (int r = 0; r < EPT; r++) spk[tid * EPT + r] = v[r];
    __syncthreads();

    // ---- phase 3: decode boxes into sorted order (pinned IEEE, no FMA) ----
    for (int p = tid; p < NPRI; p += BLK) {
        int n = NPRI - 1 - (int)(unsigned)(spk[p] & 0xffffffffu);
        const float* lp = loc + ((size_t)b * NPRI + n) * 4;
        float lx = lp[0], ly = lp[1], lw = lp[2], lh = lp[3];
        float pcx = prior[n * 4 + 0], pcy = prior[n * 4 + 1];
        float pw  = prior[n * 4 + 2], ph  = prior[n * 4 + 3];

        float cx = __fadd_rn(pcx, __fmul_rn(__fmul_rn(lx, 0.1f), pw));
        float cy = __fadd_rn(pcy, __fmul_rn(__fmul_rn(ly, 0.1f), ph));
        float w  = __fmul_rn(pw, expf(__fmul_rn(lw, 0.2f)));
        float h  = __fmul_rn(ph, expf(__fmul_rn(lh, 0.2f)));
        float hw = __fmul_rn(w, 0.5f);
        float hh = __fmul_rn(h, 0.5f);
        float x1 = __fsub_rn(cx, hw), y1 = __fsub_rn(cy, hh);
        float x2 = __fadd_rn(cx, hw), y2 = __fadd_rn(cy, hh);

        sbox[p]  = make_float4(x1, y1, x2, y2);
        sarea[p] = __fmul_rn(__fsub_rn(x2, x1), __fsub_rn(y2, y1));
    }
    __syncthreads();

    // ---- phase 4: greedy NMS, single warp, kept set in registers ----
    // kept box k lives at lane (k & 31), register slot (k >> 5); kept < 200 -> <= 7 slots
    if (tid < 32) {
        float4 kb[7];
        float  ka[7];
        int kept = 0;

        for (int i = 0; i < NPRI && kept < TOPK; i++) {
            u64 pk  = spk[i];                                   // smem broadcast
            float s = __uint_as_float((unsigned)(pk >> 32));
            if (!(s > CONF_TH)) break;                          // sorted desc

            float4 bi = sbox[i];
            float  ai = sarea[i];

            bool sup = false;
            #pragma unroll
            for (int r = 0; r < 7; r++) {
                if ((r << 5) + tid < kept) {
                    float iw = fmaxf(__fsub_rn(fminf(bi.z, kb[r].z), fmaxf(bi.x, kb[r].x)), 0.0f);
                    float ih = fmaxf(__fsub_rn(fminf(bi.w, kb[r].w), fmaxf(bi.y, kb[r].y)), 0.0f);
                    float inter = __fmul_rn(iw, ih);
                    float denom = __fsub_rn(__fadd_rn(ka[r], ai), inter);
                    sup |= (__fdiv_rn(inter, denom) > NMS_TH);
                }
            }
            if (__any_sync(0xffffffffu, sup)) continue;

            #pragma unroll
            for (int r = 0; r < 7; r++) {
                if ((kept >> 5) == r && (kept & 31) == tid) { kb[r] = bi; ka[r] = ai; }
            }
            if (tid == 0) {
                float* row = ob + (size_t)(TOPK + kept) * 5;    // class-1 slice
                row[0] = s;
                row[1] = bi.x; row[2] = bi.y; row[3] = bi.z; row[4] = bi.w;
            }
            kept++;
        }
    }
}

extern "C" void kernel_launch(void* const* d_in, const int* in_sizes, int n_in,
                              void* d_out, int out_size)
{
    const float* loc   = (const float*)d_in[0];
    const float* conf  = (const float*)d_in[1];
    const float* prior = (const float*)d_in[2];
    float* out = (float*)d_out;

    cudaFuncSetAttribute(post_rois_kernel,
                         cudaFuncAttributeMaxDynamicSharedMemorySize, SMEM_BYTES);
    post_rois_kernel<<<BATCH, BLK, SMEM_BYTES>>>(loc, conf, prior, out);
}

// round 5
// speedup vs baseline: 1.8939x; 1.8925x over previous
#include <cuda_runtime.h>
#include <math.h>

// Post_rois: SSD post-processing (softmax scores + box decode + greedy NMS + top-200)
// Inputs: loc [8,4096,4] f32, conf [8*4096,2] f32, prior [4096,4] f32 (cx,cy,w,h)
// Output: f32 [8, 2, 200, 5]; class-0 slice zeros, class-1 = NMS rows [s,x1,y1,x2,y2].

#define BATCH    8
#define NPRI     4096
#define TOPK     200
#define BLK      512      // 8 elements per thread in sort; 1 candidate/thread in NMS
#define EPT      8
#define CHUNK    512
#define NWORD    16       // CHUNK/32
#define CONF_TH  0.01f
#define NMS_TH   0.45f

typedef unsigned long long u64;

// ---------------- dynamic smem layout ----------------
// float4 sbox [4096]  65536 B   (offset 0)
// u64    spk  [4096]  32768 B
// float  sarea[4096]  16384 B
// u32    mask [512][16] 32768 B
// float4 abox [512]    8192 B
// float  aarea[512]    2048 B
// float  ascore[512]   2048 B
// float4 kbox [200]    3200 B
// float  karea[200]     800 B
#define OFF_SBOX   0
#define OFF_SPK    (OFF_SBOX  + NPRI * 16)
#define OFF_SAREA  (OFF_SPK   + NPRI * 8)
#define OFF_MASK   (OFF_SAREA + NPRI * 4)
#define OFF_ABOX   (OFF_MASK  + CHUNK * NWORD * 4)
#define OFF_AAREA  (OFF_ABOX  + CHUNK * 16)
#define OFF_ASCORE (OFF_AAREA + CHUNK * 4)
#define OFF_KBOX   (OFF_ASCORE+ CHUNK * 4)
#define OFF_KAREA  (OFF_KBOX  + TOPK * 16)
#define SMEM_BYTES (OFF_KAREA + TOPK * 4)

// compare-exchange: a is the LOWER-index element. desc=true -> a gets the max.
__device__ __forceinline__ void ce(u64 &a, u64 &b, bool desc) {
    u64 lo = a < b ? a : b;
    u64 hi = a < b ? b : a;
    a = desc ? hi : lo;
    b = desc ? lo : hi;
}

__device__ __forceinline__ void local_merge8(u64 v[EPT], bool d) {
    ce(v[0],v[4],d); ce(v[1],v[5],d); ce(v[2],v[6],d); ce(v[3],v[7],d);
    ce(v[0],v[2],d); ce(v[1],v[3],d); ce(v[4],v[6],d); ce(v[5],v[7],d);
    ce(v[0],v[1],d); ce(v[2],v[3],d); ce(v[4],v[5],d); ce(v[6],v[7],d);
}

__device__ __forceinline__ void local_sort8(u64 v[EPT], bool dir8) {
    ce(v[0],v[1],true);  ce(v[2],v[3],false); ce(v[4],v[5],true);  ce(v[6],v[7],false);
    ce(v[0],v[2],true);  ce(v[1],v[3],true);  ce(v[4],v[6],false); ce(v[5],v[7],false);
    ce(v[0],v[1],true);  ce(v[2],v[3],true);  ce(v[4],v[5],false); ce(v[6],v[7],false);
    local_merge8(v, dir8);
}

__device__ __forceinline__ void shfl_stage(u64 v[EPT], int d, bool dirT, int tid) {
    bool keep_max = (((tid & d) == 0) == dirT);
    #pragma unroll
    for (int r = 0; r < EPT; r++) {
        u64 o = __shfl_xor_sync(0xffffffffu, v[r], d);
        v[r] = keep_max ? (v[r] > o ? v[r] : o) : (v[r] < o ? v[r] : o);
    }
}

__global__ __launch_bounds__(BLK, 1)
void post_rois_kernel(const float* __restrict__ loc,
                      const float* __restrict__ conf,
                      const float* __restrict__ prior,
                      float* __restrict__ out)
{
    const int b    = blockIdx.x;
    const int tid  = threadIdx.x;
    const int wid  = tid >> 5;
    const int lane = tid & 31;

    extern __shared__ unsigned char smem_raw[];
    float4*   sbox   = (float4*)(smem_raw + OFF_SBOX);
    u64*      spk    = (u64*)   (smem_raw + OFF_SPK);
    float*    sarea  = (float*) (smem_raw + OFF_SAREA);
    unsigned* maskm  = (unsigned*)(smem_raw + OFF_MASK);   // [CHUNK][NWORD]
    float4*   abox   = (float4*)(smem_raw + OFF_ABOX);
    float*    aarea  = (float*) (smem_raw + OFF_AAREA);
    float*    ascore = (float*) (smem_raw + OFF_ASCORE);
    float4*   kbox   = (float4*)(smem_raw + OFF_KBOX);
    float*    karea  = (float*) (smem_raw + OFF_KAREA);

    __shared__ int wcnt[16], wbase[17];
    __shared__ int skept;

    // ---- zero this image's output slice ----
    float* ob = out + (size_t)b * 2 * TOPK * 5;
    for (int i = tid; i < 2 * TOPK * 5; i += BLK) ob[i] = 0.0f;
    if (tid == 0) skept = 0;

    // ---- phase 1: softmax scores, pack into sortable u64 ----
    for (int n = tid; n < NPRI; n += BLK) {
        float c0 = conf[((size_t)b * NPRI + n) * 2 + 0];
        float c1 = conf[((size_t)b * NPRI + n) * 2 + 1];
        float m  = fmaxf(c0, c1);
        float e0 = expf(__fsub_rn(c0, m));
        float e1 = expf(__fsub_rn(c1, m));
        float s  = __fdiv_rn(e1, __fadd_rn(e0, e1));
        spk[n] = ((u64)__float_as_uint(s) << 32) | (unsigned)(NPRI - 1 - n);
    }
    __syncthreads();

    // ---- phase 2: bitonic sort (descending), 8 elems/thread in registers ----
    u64 v[EPT];
    #pragma unroll
    for (int r = 0; r < EPT; r++) v[r] = spk[tid * EPT + r];

    local_sort8(v, (tid & 1) == 0);

    for (int k = 16; k <= 256; k <<= 1) {
        bool dirT = ((tid & (k >> 3)) == 0);
        for (int d = (k >> 4); d >= 1; d >>= 1) shfl_stage(v, d, dirT, tid);
        local_merge8(v, dirT);
    }

    for (int k = 512; k <= (int)NPRI; k <<= 1) {
        #pragma unroll
        for (int r = 0; r < EPT; r++) spk[tid * EPT + r] = v[r];
        __syncthreads();
        for (int j = (k >> 1); j >= 256; j >>= 1) {
            for (int m = tid; m < NPRI / 2; m += BLK) {
                int i = ((m & ~(j - 1)) << 1) | (m & (j - 1));
                int p = i | j;
                u64 a = spk[i], c = spk[p];
                bool desc = ((i & k) == 0);
                if (desc ? (a < c) : (a > c)) { spk[i] = c; spk[p] = a; }
            }
            __syncthreads();
        }
        #pragma unroll
        for (int r = 0; r < EPT; r++) v[r] = spk[tid * EPT + r];
        bool dirT = ((tid & (k >> 3)) == 0);
        for (int d = 16; d >= 1; d >>= 1) shfl_stage(v, d, dirT, tid);
        local_merge8(v, dirT);
    }

    #pragma unroll
    for (int r = 0; r < EPT; r++) spk[tid * EPT + r] = v[r];
    __syncthreads();

    // ---- phase 3: decode boxes into sorted order (pinned IEEE, no FMA) ----
    for (int p = tid; p < NPRI; p += BLK) {
        int n = NPRI - 1 - (int)(unsigned)(spk[p] & 0xffffffffu);
        const float* lp = loc + ((size_t)b * NPRI + n) * 4;
        float lx = lp[0], ly = lp[1], lw = lp[2], lh = lp[3];
        float pcx = prior[n * 4 + 0], pcy = prior[n * 4 + 1];
        float pw  = prior[n * 4 + 2], ph  = prior[n * 4 + 3];

        float cx = __fadd_rn(pcx, __fmul_rn(__fmul_rn(lx, 0.1f), pw));
        float cy = __fadd_rn(pcy, __fmul_rn(__fmul_rn(ly, 0.1f), ph));
        float w  = __fmul_rn(pw, expf(__fmul_rn(lw, 0.2f)));
        float h  = __fmul_rn(ph, expf(__fmul_rn(lh, 0.2f)));
        float hw = __fmul_rn(w, 0.5f);
        float hh = __fmul_rn(h, 0.5f);
        float x1 = __fsub_rn(cx, hw), y1 = __fsub_rn(cy, hh);
        float x2 = __fadd_rn(cx, hw), y2 = __fadd_rn(cy, hh);

        sbox[p]  = make_float4(x1, y1, x2, y2);
        sarea[p] = __fmul_rn(__fsub_rn(x2, x1), __fsub_rn(y2, y1));
    }
    __syncthreads();

    // ---- phase 4: chunked bitmask NMS (exact greedy, exact reference math) ----
    for (int c0 = 0; c0 < NPRI; c0 += CHUNK) {
        if (skept >= TOPK) break;
        // chunk's best score; sorted desc, so if it's invalid all the rest are too
        float topS = __uint_as_float((unsigned)(spk[c0] >> 32));
        if (!(topS > CONF_TH)) break;

        // --- step 0/1: load candidate, test vs already-kept set ---
        int   i  = c0 + tid;
        float s  = __uint_as_float((unsigned)(spk[i] >> 32));
        bool  ok = (s > CONF_TH);
        float4 bi = sbox[i];
        float  ai = sarea[i];

        int K = skept;
        for (int k = 0; k < K; k++) {
            if (__all_sync(0xffffffffu, !ok)) break;
            if (ok) {
                float4 bj = kbox[k];
                float iw = fmaxf(__fsub_rn(fminf(bi.z, bj.z), fmaxf(bi.x, bj.x)), 0.0f);
                float ih = fmaxf(__fsub_rn(fminf(bi.w, bj.w), fmaxf(bi.y, bj.y)), 0.0f);
                float inter = __fmul_rn(iw, ih);
                if (inter > 0.0f) {
                    float denom = __fsub_rn(__fadd_rn(karea[k], ai), inter);
                    if (__fdiv_rn(inter, denom) > NMS_TH) ok = false;
                }
            }
        }

        // --- order-preserving compaction of survivors ---
        unsigned bal = __ballot_sync(0xffffffffu, ok);
        if (lane == 0) wcnt[wid] = __popc(bal);
        __syncthreads();
        if (tid == 0) {
            int acc = 0;
            for (int w = 0; w < 16; w++) { wbase[w] = acc; acc += wcnt[w]; }
            wbase[16] = acc;
        }
        __syncthreads();
        int A = wbase[16];
        if (ok) {
            int pos = wbase[wid] + __popc(bal & ((1u << lane) - 1));
            abox[pos]   = bi;
            aarea[pos]  = ai;
            ascore[pos] = s;
        }
        __syncthreads();

        if (A > 0) {
            // --- step 2: pairwise suppression mask, row r covers j > r ---
            if (tid < A) {
                float4 br = abox[tid];
                float  ar = aarea[tid];
                #pragma unroll 1
                for (int w = 0; w < NWORD; w++) {
                    unsigned bits = 0;
                    int jbase = w << 5;
                    if (jbase + 31 > tid && jbase < A) {
                        int jend = (A - jbase < 32) ? (A - jbase) : 32;
                        for (int jj = 0; jj < jend; jj++) {
                            int j = jbase + jj;
                            if (j > tid) {
                                float4 bj = abox[j];
                                float iw = fmaxf(__fsub_rn(fminf(br.z, bj.z), fmaxf(br.x, bj.x)), 0.0f);
                                float ih = fmaxf(__fsub_rn(fminf(br.w, bj.w), fmaxf(br.y, bj.y)), 0.0f);
                                float inter = __fmul_rn(iw, ih);
                                if (inter > 0.0f) {
                                    float denom = __fsub_rn(__fadd_rn(ar, aarea[j]), inter);
                                    if (__fdiv_rn(inter, denom) > NMS_TH) bits |= (1u << jj);
                                }
                            }
                        }
                    }
                    maskm[tid * NWORD + w] = bits;
                }
            }
            __syncthreads();

            // --- step 3: sweep by warp 0 ---
            if (tid < 32) {
                unsigned supw = 0;                 // lane l < 16 owns bits [32l, 32l+32)
                int kept = skept;
                for (int r = 0; r < A; r++) {
                    unsigned wsrc = __shfl_sync(0xffffffffu, supw, r >> 5);
                    if (!((wsrc >> (r & 31)) & 1u)) {
                        if (lane < NWORD) supw |= maskm[r * NWORD + lane];
                        if (lane == 0) {
                            float4 bb = abox[r];
                            kbox[kept]  = bb;
                            karea[kept] = aarea[r];
                            float* row = ob + (size_t)(TOPK + kept) * 5;
                            row[0] = ascore[r];
                            row[1] = bb.x; row[2] = bb.y; row[3] = bb.z; row[4] = bb.w;
                        }
                        kept++;
                        if (kept == TOPK) break;
                    }
                }
                if (lane == 0) skept = kept;
            }
        }
        __syncthreads();
    }
}

extern "C" void kernel_launch(void* const* d_in, const int* in_sizes, int n_in,
                              void* d_out, int out_size)
{
    const float* loc   = (const float*)d_in[0];
    const float* conf  = (const float*)d_in[1];
    const float* prior = (const float*)d_in[2];
    float* out = (float*)d_out;

    cudaFuncSetAttribute(post_rois_kernel,
                         cudaFuncAttributeMaxDynamicSharedMemorySize, SMEM_BYTES);
    post_rois_kernel<<<BATCH, BLK, SMEM_BYTES>>>(loc, conf, prior, out);
}

// round 10
// speedup vs baseline: 2.7321x; 1.4426x over previous
#include <cuda_runtime.h>
#include <math.h>

// Post_rois: SSD post-processing (softmax scores + box decode + greedy NMS + top-200)
// Inputs: loc [8,4096,4] f32, conf [8*4096,2] f32, prior [4096,4] f32 (cx,cy,w,h)
// Output: f32 [8, 2, 200, 5]; class-0 slice zeros, class-1 = NMS rows [s,x1,y1,x2,y2].

#define BATCH    8
#define NPRI     4096
#define TOPK     200
#define BLK      512      // 8 elements/thread in sort; 1 candidate/thread in NMS
#define EPT      8
#define CHUNK    512
#define NWORD    16       // CHUNK/32
#define CONF_TH  0.01f
#define NMS_TH   0.45f

typedef unsigned long long u64;

// ---------------- dynamic smem layout ----------------
#define OFF_SBOX   0
#define OFF_SPK    (OFF_SBOX  + NPRI * 16)
#define OFF_SAREA  (OFF_SPK   + NPRI * 8)
#define OFF_ABOX   (OFF_SAREA + NPRI * 4)
#define OFF_AAREA  (OFF_ABOX  + CHUNK * 16)
#define OFF_ASCORE (OFF_AAREA + CHUNK * 4)
#define OFF_KBOX   (OFF_ASCORE+ CHUNK * 4)
#define OFF_KAREA  (OFF_KBOX  + TOPK * 16)
#define SMEM_BYTES (OFF_KAREA + TOPK * 4)

// compare-exchange: a is the LOWER-index element. desc=true -> a gets the max.
__device__ __forceinline__ void ce(u64 &a, u64 &b, bool desc) {
    u64 lo = a < b ? a : b;
    u64 hi = a < b ? b : a;
    a = desc ? hi : lo;
    b = desc ? lo : hi;
}

__device__ __forceinline__ void local_merge8(u64 v[EPT], bool d) {
    ce(v[0],v[4],d); ce(v[1],v[5],d); ce(v[2],v[6],d); ce(v[3],v[7],d);
    ce(v[0],v[2],d); ce(v[1],v[3],d); ce(v[4],v[6],d); ce(v[5],v[7],d);
    ce(v[0],v[1],d); ce(v[2],v[3],d); ce(v[4],v[5],d); ce(v[6],v[7],d);
}

__device__ __forceinline__ void local_sort8(u64 v[EPT], bool dir8) {
    ce(v[0],v[1],true);  ce(v[2],v[3],false); ce(v[4],v[5],true);  ce(v[6],v[7],false);
    ce(v[0],v[2],true);  ce(v[1],v[3],true);  ce(v[4],v[6],false); ce(v[5],v[7],false);
    ce(v[0],v[1],true);  ce(v[2],v[3],true);  ce(v[4],v[5],false); ce(v[6],v[7],false);
    local_merge8(v, dir8);
}

__device__ __forceinline__ void shfl_stage(u64 v[EPT], int d, bool dirT, int tid) {
    bool keep_max = (((tid & d) == 0) == dirT);
    #pragma unroll
    for (int r = 0; r < EPT; r++) {
        u64 o = __shfl_xor_sync(0xffffffffu, v[r], d);
        v[r] = keep_max ? (v[r] > o ? v[r] : o) : (v[r] < o ? v[r] : o);
    }
}

__global__ __launch_bounds__(BLK, 1)
void post_rois_kernel(const float* __restrict__ loc,
                      const float* __restrict__ conf,
                      const float* __restrict__ prior,
                      float* __restrict__ out)
{
    const int b    = blockIdx.x;
    const int tid  = threadIdx.x;
    const int wid  = tid >> 5;
    const int lane = tid & 31;

    extern __shared__ unsigned char smem_raw[];
    float4*   sbox   = (float4*)(smem_raw + OFF_SBOX);
    u64*      spk    = (u64*)   (smem_raw + OFF_SPK);
    float*    sarea  = (float*) (smem_raw + OFF_SAREA);
    float4*   abox   = (float4*)(smem_raw + OFF_ABOX);
    float*    aarea  = (float*) (smem_raw + OFF_AAREA);
    float*    ascore = (float*) (smem_raw + OFF_ASCORE);
    float4*   kbox   = (float4*)(smem_raw + OFF_KBOX);
    float*    karea  = (float*) (smem_raw + OFF_KAREA);

    __shared__ int wcnt[16], wbase[17];
    __shared__ unsigned supvec[16];
    __shared__ int skept;

    // ---- zero this image's output slice ----
    float* ob = out + (size_t)b * 2 * TOPK * 5;
    for (int i = tid; i < 2 * TOPK * 5; i += BLK) ob[i] = 0.0f;
    if (tid == 0) skept = 0;

    // ---- phase 1: softmax scores, pack into sortable u64 ----
    for (int n = tid; n < NPRI; n += BLK) {
        float c0 = conf[((size_t)b * NPRI + n) * 2 + 0];
        float c1 = conf[((size_t)b * NPRI + n) * 2 + 1];
        float m  = fmaxf(c0, c1);
        float e0 = expf(__fsub_rn(c0, m));
        float e1 = expf(__fsub_rn(c1, m));
        float s  = __fdiv_rn(e1, __fadd_rn(e0, e1));
        spk[n] = ((u64)__float_as_uint(s) << 32) | (unsigned)(NPRI - 1 - n);
    }
    __syncthreads();

    // ---- phase 2: bitonic sort (descending), 8 elems/thread in registers ----
    u64 v[EPT];
    #pragma unroll
    for (int r = 0; r < EPT; r++) v[r] = spk[tid * EPT + r];

    local_sort8(v, (tid & 1) == 0);

    for (int k = 16; k <= 256; k <<= 1) {
        bool dirT = ((tid & (k >> 3)) == 0);
        for (int d = (k >> 4); d >= 1; d >>= 1) shfl_stage(v, d, dirT, tid);
        local_merge8(v, dirT);
    }

    for (int k = 512; k <= (int)NPRI; k <<= 1) {
        #pragma unroll
        for (int r = 0; r < EPT; r++) spk[tid * EPT + r] = v[r];
        __syncthreads();
        for (int j = (k >> 1); j >= 256; j >>= 1) {
            for (int m = tid; m < NPRI / 2; m += BLK) {
                int i = ((m & ~(j - 1)) << 1) | (m & (j - 1));
                int p = i | j;
                u64 a = spk[i], c = spk[p];
                bool desc = ((i & k) == 0);
                if (desc ? (a < c) : (a > c)) { spk[i] = c; spk[p] = a; }
            }
            __syncthreads();
        }
        #pragma unroll
        for (int r = 0; r < EPT; r++) v[r] = spk[tid * EPT + r];
        bool dirT = ((tid & (k >> 3)) == 0);
        for (int d = 16; d >= 1; d >>= 1) shfl_stage(v, d, dirT, tid);
        local_merge8(v, dirT);
    }

    #pragma unroll
    for (int r = 0; r < EPT; r++) spk[tid * EPT + r] = v[r];
    __syncthreads();

    // ---- phase 3: decode boxes into sorted order (pinned IEEE, no FMA) ----
    for (int p = tid; p < NPRI; p += BLK) {
        int n = NPRI - 1 - (int)(unsigned)(spk[p] & 0xffffffffu);
        const float* lp = loc + ((size_t)b * NPRI + n) * 4;
        float lx = lp[0], ly = lp[1], lw = lp[2], lh = lp[3];
        float pcx = prior[n * 4 + 0], pcy = prior[n * 4 + 1];
        float pw  = prior[n * 4 + 2], ph  = prior[n * 4 + 3];

        float cx = __fadd_rn(pcx, __fmul_rn(__fmul_rn(lx, 0.1f), pw));
        float cy = __fadd_rn(pcy, __fmul_rn(__fmul_rn(ly, 0.1f), ph));
        float w  = __fmul_rn(pw, expf(__fmul_rn(lw, 0.2f)));
        float h  = __fmul_rn(ph, expf(__fmul_rn(lh, 0.2f)));
        float hw = __fmul_rn(w, 0.5f);
        float hh = __fmul_rn(h, 0.5f);
        float x1 = __fsub_rn(cx, hw), y1 = __fsub_rn(cy, hh);
        float x2 = __fadd_rn(cx, hw), y2 = __fadd_rn(cy, hh);

        sbox[p]  = make_float4(x1, y1, x2, y2);
        sarea[p] = __fmul_rn(__fsub_rn(x2, x1), __fsub_rn(y2, y1));
    }
    __syncthreads();

    // ---- phase 4: chunked NMS, Jacobi-fixpoint suppression (exact greedy) ----
    for (int c0 = 0; c0 < NPRI; c0 += CHUNK) {
        if (skept >= TOPK) break;
        float topS = __uint_as_float((unsigned)(spk[c0] >> 32));
        if (!(topS > CONF_TH)) break;       // sorted desc: rest invalid too

        // --- step 1: candidate vs already-kept boxes (no-op on first chunk) ---
        int   i  = c0 + tid;
        float s  = __uint_as_float((unsigned)(spk[i] >> 32));
        bool  ok = (s > CONF_TH);
        float4 bi = sbox[i];
        float  ai = sarea[i];

        int K = skept;
        for (int k = 0; k < K; k++) {
            if (__all_sync(0xffffffffu, !ok)) break;
            if (ok) {
                float4 bj = kbox[k];
                float iw = fmaxf(__fsub_rn(fminf(bi.z, bj.z), fmaxf(bi.x, bj.x)), 0.0f);
                float ih = fmaxf(__fsub_rn(fminf(bi.w, bj.w), fmaxf(bi.y, bj.y)), 0.0f);
                float inter = __fmul_rn(iw, ih);
                if (inter > 0.0f) {
                    float denom = __fsub_rn(__fadd_rn(karea[k], ai), inter);
                    if (__fdiv_rn(inter, denom) > NMS_TH) ok = false;
                }
            }
        }

        // --- order-preserving compaction of survivors ---
        unsigned bal = __ballot_sync(0xffffffffu, ok);
        if (lane == 0) wcnt[wid] = __popc(bal);
        __syncthreads();
        if (tid == 0) {
            int acc = 0;
            for (int w = 0; w < 16; w++) { wbase[w] = acc; acc += wcnt[w]; }
            wbase[16] = acc;
        }
        __syncthreads();
        int A = wbase[16];
        if (ok) {
            int pos = wbase[wid] + __popc(bal & ((1u << lane) - 1));
            abox[pos]   = bi;
            aarea[pos]  = ai;
            ascore[pos] = s;
        }
        __syncthreads();
        if (A == 0) continue;

        // --- step 2: suppressor mask, COLUMN-major in registers ---
        // thread i holds bit r (r < i) set iff iou(r, i) > NMS_TH
        unsigned mT[NWORD];
        float4 bc = abox[tid < A ? tid : 0];
        float  ac = aarea[tid < A ? tid : 0];
        #pragma unroll
        for (int w = 0; w < NWORD; w++) {
            unsigned bits = 0;
            int rbase = w << 5;
            if (tid < A && rbase < tid) {
                int rend = tid - rbase; if (rend > 32) rend = 32;
                for (int rr = 0; rr < rend; rr++) {
                    float4 br = abox[rbase + rr];          // broadcast LDS
                    float iw = fmaxf(__fsub_rn(fminf(bc.z, br.z), fmaxf(bc.x, br.x)), 0.0f);
                    float ih = fmaxf(__fsub_rn(fminf(bc.w, br.w), fmaxf(bc.y, br.y)), 0.0f);
                    float inter = __fmul_rn(iw, ih);
                    if (inter > 0.0f) {
                        float denom = __fsub_rn(__fadd_rn(aarea[rbase + rr], ac), inter);
                        if (__fdiv_rn(inter, denom) > NMS_TH) bits |= (1u << rr);
                    }
                }
            }
            mT[w] = bits;
        }

        // --- step 3: Jacobi fixpoint of sup_i = OR_{r<i} (!sup_r & mT_i[r]) ---
        bool sup = false;
        for (int it = 0; it <= A; it++) {
            unsigned sb = __ballot_sync(0xffffffffu, sup);
            if (lane == 0) supvec[wid] = sb;
            __syncthreads();
            bool ns = false;
            #pragma unroll
            for (int w = 0; w < NWORD; w++)
                ns |= (mT[w] & ~supvec[w]) != 0;
            if (!__syncthreads_or(ns != sup)) break;   // converged (uniform exit)
            sup = ns;
        }

        // --- ordered compaction of kept, parallel output + kept-set append ---
        bool kept = (tid < A) && !sup;
        unsigned kb = __ballot_sync(0xffffffffu, kept);
        if (lane == 0) wcnt[wid] = __popc(kb);
        __syncthreads();
        if (tid == 0) {
            int acc = 0;
            for (int w = 0; w < 16; w++) { wbase[w] = acc; acc += wcnt[w]; }
            wbase[16] = acc;
        }
        __syncthreads();
        int total = wbase[16];
        if (kept) {
            int pos = skept + wbase[wid] + __popc(kb & ((1u << lane) - 1));
            if (pos < TOPK) {
                kbox[pos]  = bc;
                karea[pos] = ac;
                float* row = ob + (size_t)(TOPK + pos) * 5;   // class-1 slice
                row[0] = ascore[tid];
                row[1] = bc.x; row[2] = bc.y; row[3] = bc.z; row[4] = bc.w;
            }
        }
        __syncthreads();
        if (tid == 0) {
            int nk = skept + total;
            skept = nk < TOPK ? nk : TOPK;
        }
        __syncthreads();
    }
}

extern "C" void kernel_launch(void* const* d_in, const int* in_sizes, int n_in,
                              void* d_out, int out_size)
{
    const float* loc   = (const float*)d_in[0];
    const float* conf  = (const float*)d_in[1];
    const float* prior = (const float*)d_in[2];
    float* out = (float*)d_out;

    cudaFuncSetAttribute(post_rois_kernel,
                         cudaFuncAttributeMaxDynamicSharedMemorySize, SMEM_BYTES);
    post_rois_kernel<<<BATCH, BLK, SMEM_BYTES>>>(loc, conf, prior, out);
}

// round 12
// speedup vs baseline: 3.6006x; 1.3179x over previous
#include <cuda_runtime.h>
#include <math.h>

// Post_rois: SSD post-processing (softmax scores + box decode + greedy NMS + top-200)
// Inputs: loc [8,4096,4] f32, conf [8*4096,2] f32, prior [4096,4] f32 (cx,cy,w,h)
// Output: f32 [8, 2, 200, 5]; class-0 slice zeros, class-1 = NMS rows [s,x1,y1,x2,y2].

#define BATCH    8
#define NPRI     4096
#define TOPK     200
#define BLK      1024     // 4 elements/thread in sort; 2 threads/candidate in NMS
#define EPT      4
#define CHUNK    512
#define NWORD    16       // CHUNK/32
#define HWORD    8        // NWORD/2 : words per (primary|helper)
#define CONF_TH  0.01f
#define NMS_TH   0.45f

typedef unsigned long long u64;

// ---------------- dynamic smem layout ----------------
#define OFF_SBOX   0
#define OFF_SPK    (OFF_SBOX  + NPRI * 16)
#define OFF_SAREA  (OFF_SPK   + NPRI * 8)
#define OFF_ABOX   (OFF_SAREA + NPRI * 4)
#define OFF_AAREA  (OFF_ABOX  + CHUNK * 16)
#define OFF_ASCORE (OFF_AAREA + CHUNK * 4)
#define OFF_KBOX   (OFF_ASCORE+ CHUNK * 4)
#define OFF_KAREA  (OFF_KBOX  + TOPK * 16)
#define SMEM_BYTES (OFF_KAREA + TOPK * 4)

// compare-exchange: a is the LOWER-index element. desc=true -> a gets the max.
__device__ __forceinline__ void ce(u64 &a, u64 &b, bool desc) {
    u64 lo = a < b ? a : b;
    u64 hi = a < b ? b : a;
    a = desc ? hi : lo;
    b = desc ? lo : hi;
}

// merge of a 4-element bitonic sequence, uniform direction (j = 2, 1)
__device__ __forceinline__ void local_merge4(u64 v[EPT], bool d) {
    ce(v[0],v[2],d); ce(v[1],v[3],d);
    ce(v[0],v[1],d); ce(v[2],v[3],d);
}

// phases k=2,4 within one thread's 4 contiguous elements (i = 4*tid + r)
__device__ __forceinline__ void local_sort4(u64 v[EPT], bool dir4) {
    ce(v[0],v[1],true);  ce(v[2],v[3],false);   // k=2
    ce(v[0],v[2],dir4);  ce(v[1],v[3],dir4);    // k=4, j=2
    ce(v[0],v[1],dir4);  ce(v[2],v[3],dir4);    // k=4, j=1
}

// cross-thread (within-warp) stage j = 4*d via shfl.xor; dir uniform per thread
__device__ __forceinline__ void shfl_stage4(u64 v[EPT], int d, bool dirT, int tid) {
    bool keep_max = (((tid & d) == 0) == dirT);
    #pragma unroll
    for (int r = 0; r < EPT; r++) {
        u64 o = __shfl_xor_sync(0xffffffffu, v[r], d);
        v[r] = keep_max ? (v[r] > o ? v[r] : o) : (v[r] < o ? v[r] : o);
    }
}

__global__ __launch_bounds__(BLK, 1)
void post_rois_kernel(const float* __restrict__ loc,
                      const float* __restrict__ conf,
                      const float* __restrict__ prior,
                      float* __restrict__ out)
{
    const int b    = blockIdx.x;
    const int tid  = threadIdx.x;
    const int wid  = tid >> 5;
    const int lane = tid & 31;

    extern __shared__ unsigned char smem_raw[];
    float4*   sbox   = (float4*)(smem_raw + OFF_SBOX);
    u64*      spk    = (u64*)   (smem_raw + OFF_SPK);
    float*    sarea  = (float*) (smem_raw + OFF_SAREA);
    float4*   abox   = (float4*)(smem_raw + OFF_ABOX);
    float*    aarea  = (float*) (smem_raw + OFF_AAREA);
    float*    ascore = (float*) (smem_raw + OFF_ASCORE);
    float4*   kbox   = (float4*)(smem_raw + OFF_KBOX);
    float*    karea  = (float*) (smem_raw + OFF_KAREA);

    __shared__ int wcnt[16], wbase[17];
    __shared__ unsigned supvec[NWORD];
    __shared__ unsigned char hsup[CHUNK];   // helper: suppressed-by-kept-set flag
    __shared__ unsigned char hns[CHUNK];    // helper: Jacobi partial next-sup
    __shared__ int skept;

    const bool primary = tid < CHUNK;
    const int  ci      = tid & (CHUNK - 1);   // candidate index within chunk

    // ---- zero this image's output slice ----
    float* ob = out + (size_t)b * 2 * TOPK * 5;
    for (int i = tid; i < 2 * TOPK * 5; i += BLK) ob[i] = 0.0f;
    if (tid == 0) skept = 0;

    // ---- phase 1: softmax scores, pack into sortable u64 ----
    for (int n = tid; n < NPRI; n += BLK) {
        float c0 = conf[((size_t)b * NPRI + n) * 2 + 0];
        float c1 = conf[((size_t)b * NPRI + n) * 2 + 1];
        float m  = fmaxf(c0, c1);
        float e0 = expf(__fsub_rn(c0, m));
        float e1 = expf(__fsub_rn(c1, m));
        float s  = __fdiv_rn(e1, __fadd_rn(e0, e1));
        spk[n] = ((u64)__float_as_uint(s) << 32) | (unsigned)(NPRI - 1 - n);
    }
    __syncthreads();

    // ---- phase 2: bitonic sort (descending), 4 elems/thread in registers ----
    u64 v[EPT];
    #pragma unroll
    for (int r = 0; r < EPT; r++) v[r] = spk[tid * EPT + r];

    local_sort4(v, (tid & 1) == 0);                       // k = 2, 4

    for (int k = 8; k <= 128; k <<= 1) {                  // fully warp-local
        bool dirT = ((tid & (k >> 2)) == 0);
        for (int d = (k >> 3); d >= 1; d >>= 1) shfl_stage4(v, d, dirT, tid);
        local_merge4(v, dirT);
    }

    for (int k = 256; k <= (int)NPRI; k <<= 1) {          // cross-warp phases
        #pragma unroll
        for (int r = 0; r < EPT; r++) spk[tid * EPT + r] = v[r];
        __syncthreads();
        for (int j = (k >> 1); j >= 128; j >>= 1) {       // smem stages
            for (int m = tid; m < NPRI / 2; m += BLK) {
                int i = ((m & ~(j - 1)) << 1) | (m & (j - 1));
                int p = i | j;
                u64 a = spk[i], c = spk[p];
                bool desc = ((i & k) == 0);
                if (desc ? (a < c) : (a > c)) { spk[i] = c; spk[p] = a; }
            }
            __syncthreads();
        }
        #pragma unroll
        for (int r = 0; r < EPT; r++) v[r] = spk[tid * EPT + r];
        bool dirT = ((tid & (k >> 2)) == 0);
        for (int d = 16; d >= 1; d >>= 1) shfl_stage4(v, d, dirT, tid);
        local_merge4(v, dirT);
    }

    #pragma unroll
    for (int r = 0; r < EPT; r++) spk[tid * EPT + r] = v[r];
    __syncthreads();

    // ---- phase 3: decode boxes into sorted order (pinned IEEE, no FMA) ----
    for (int p = tid; p < NPRI; p += BLK) {
        int n = NPRI - 1 - (int)(unsigned)(spk[p] & 0xffffffffu);
        const float* lp = loc + ((size_t)b * NPRI + n) * 4;
        float lx = lp[0], ly = lp[1], lw = lp[2], lh = lp[3];
        float pcx = prior[n * 4 + 0], pcy = prior[n * 4 + 1];
        float pw  = prior[n * 4 + 2], ph  = prior[n * 4 + 3];

        float cx = __fadd_rn(pcx, __fmul_rn(__fmul_rn(lx, 0.1f), pw));
        float cy = __fadd_rn(pcy, __fmul_rn(__fmul_rn(ly, 0.1f), ph));
        float w  = __fmul_rn(pw, expf(__fmul_rn(lw, 0.2f)));
        float h  = __fmul_rn(ph, expf(__fmul_rn(lh, 0.2f)));
        float hw = __fmul_rn(w, 0.5f);
        float hh = __fmul_rn(h, 0.5f);
        float x1 = __fsub_rn(cx, hw), y1 = __fsub_rn(cy, hh);
        float x2 = __fadd_rn(cx, hw), y2 = __fadd_rn(cy, hh);

        sbox[p]  = make_float4(x1, y1, x2, y2);
        sarea[p] = __fmul_rn(__fsub_rn(x2, x1), __fsub_rn(y2, y1));
    }
    __syncthreads();

    // ---- phase 4: chunked NMS, 2 threads/candidate, Jacobi fixpoint ----
    for (int c0 = 0; c0 < NPRI; c0 += CHUNK) {
        if (skept >= TOPK) break;
        float topS = __uint_as_float((unsigned)(spk[c0] >> 32));
        if (!(topS > CONF_TH)) break;       // sorted desc: rest invalid too

        // --- step 1: candidate vs already-kept boxes (split even/odd k) ---
        int   gi = c0 + ci;
        float s  = __uint_as_float((unsigned)(spk[gi] >> 32));
        bool  okp = (s > CONF_TH);
        float4 bi = sbox[gi];
        float  ai = sarea[gi];

        int K = skept;
        for (int k = (primary ? 0 : 1); k < K; k += 2) {
            if (okp) {
                float4 bj = kbox[k];
                float iw = fmaxf(__fsub_rn(fminf(bi.z, bj.z), fmaxf(bi.x, bj.x)), 0.0f);
                float ih = fmaxf(__fsub_rn(fminf(bi.w, bj.w), fmaxf(bi.y, bj.y)), 0.0f);
                float inter = __fmul_rn(iw, ih);
                if (inter > 0.0f) {
                    float denom = __fsub_rn(__fadd_rn(karea[k], ai), inter);
                    if (__fdiv_rn(inter, denom) > NMS_TH) okp = false;
                }
            }
        }
        if (!primary) hsup[ci] = okp ? 0 : 1;
        __syncthreads();
        bool ok = primary && okp && (hsup[ci] == 0);

        // --- order-preserving compaction of survivors (primaries: warps 0..15) ---
        unsigned bal = __ballot_sync(0xffffffffu, ok);
        if (lane == 0 && wid < 16) wcnt[wid] = __popc(bal);
        __syncthreads();
        if (tid == 0) {
            int acc = 0;
            for (int w = 0; w < 16; w++) { wbase[w] = acc; acc += wcnt[w]; }
            wbase[16] = acc;
        }
        if (tid < NWORD) supvec[tid] = 0;
        __syncthreads();
        int A = wbase[16];
        if (ok) {
            int pos = wbase[wid] + __popc(bal & ((1u << lane) - 1));
            abox[pos]   = bi;
            aarea[pos]  = ai;
            ascore[pos] = s;
        }
        __syncthreads();
        if (A == 0) continue;

        // --- step 2: suppressor half-mask in registers ---
        // candidate ci: primary covers suppressors r in words 0..7 (r<256),
        //               helper covers words 8..15 (256<=r). Bits only for r<ci.
        unsigned mT[HWORD];
        float4 bc = abox[ci < A ? ci : 0];
        float  ac = aarea[ci < A ? ci : 0];
        const int wlo = primary ? 0 : HWORD;
        #pragma unroll
        for (int w = 0; w < HWORD; w++) {
            unsigned bits = 0;
            int rbase = (wlo + w) << 5;
            if (ci < A && rbase < ci) {
                int rend = ci - rbase; if (rend > 32) rend = 32;
                for (int rr = 0; rr < rend; rr++) {
                    float4 br = abox[rbase + rr];          // warp-uniform -> broadcast LDS
                    float iw = fmaxf(__fsub_rn(fminf(bc.z, br.z), fmaxf(bc.x, br.x)), 0.0f);
                    float ih = fmaxf(__fsub_rn(fminf(bc.w, br.w), fmaxf(bc.y, br.y)), 0.0f);
                    float inter = __fmul_rn(iw, ih);
                    if (inter > 0.0f) {
                        float denom = __fsub_rn(__fadd_rn(aarea[rbase + rr], ac), inter);
                        if (__fdiv_rn(inter, denom) > NMS_TH) bits |= (1u << rr);
                    }
                }
            }
            mT[w] = bits;
        }

        // --- step 3: Jacobi fixpoint of sup_i = OR_{r<i} (!sup_r & mT_i[r]) ---
        bool sup = false;               // tracked by primaries
        for (int it = 0; it <= A; it++) {
            // partial next-sup from this thread's half of the words
            bool nsh = false;
            #pragma unroll
            for (int w = 0; w < HWORD; w++)
                nsh |= (mT[w] & ~supvec[wlo + w]) != 0;
            if (!primary) hns[ci] = nsh ? 1 : 0;
            __syncthreads();

            bool changed = false;
            if (primary) {
                bool ns = nsh || (hns[ci] != 0);
                changed = (ns != sup);
                sup = ns;
            }
            unsigned sb = __ballot_sync(0xffffffffu, sup);
            if (lane == 0 && wid < 16) supvec[wid] = sb;
            if (!__syncthreads_or(changed)) break;   // also publishes supvec
        }

        // --- ordered compaction of kept, parallel output + kept-set append ---
        bool kept = primary && (ci < A) && !sup;
        unsigned kb = __ballot_sync(0xffffffffu, kept);
        if (lane == 0 && wid < 16) wcnt[wid] = __popc(kb);
        __syncthreads();
        if (tid == 0) {
            int acc = 0;
            for (int w = 0; w < 16; w++) { wbase[w] = acc; acc += wcnt[w]; }
            wbase[16] = acc;
        }
        __syncthreads();
        int total = wbase[16];
        if (kept) {
            int pos = skept + wbase[wid] + __popc(kb & ((1u << lane) - 1));
            if (pos < TOPK) {
                kbox[pos]  = bc;
                karea[pos] = ac;
                float* row = ob + (size_t)(TOPK + pos) * 5;   // class-1 slice
                row[0] = ascore[ci];
                row[1] = bc.x; row[2] = bc.y; row[3] = bc.z; row[4] = bc.w;
            }
        }
        __syncthreads();
        if (tid == 0) {
            int nk = skept + total;
            skept = nk < TOPK ? nk : TOPK;
        }
        __syncthreads();
    }
}

extern "C" void kernel_launch(void* const* d_in, const int* in_sizes, int n_in,
                              void* d_out, int out_size)
{
    const float* loc   = (const float*)d_in[0];
    const float* conf  = (const float*)d_in[1];
    const float* prior = (const float*)d_in[2];
    float* out = (float*)d_out;

    cudaFuncSetAttribute(post_rois_kernel,
                         cudaFuncAttributeMaxDynamicSharedMemorySize, SMEM_BYTES);
    post_rois_kernel<<<BATCH, BLK, SMEM_BYTES>>>(loc, conf, prior, out);
}

// round 13
// speedup vs baseline: 4.8512x; 1.3473x over previous
#include <cuda_runtime.h>
#include <math.h>

// Post_rois: SSD post-processing (softmax scores + box decode + greedy NMS + top-200)
// Inputs: loc [8,4096,4] f32, conf [8*4096,2] f32, prior [4096,4] f32 (cx,cy,w,h)
// Output: f32 [8, 2, 200, 5]; class-0 slice zeros, class-1 = NMS rows [s,x1,y1,x2,y2].
//
// Strategy: radix-select the exact top ~1024 packed keys (score,idx), bitonic-sort
// only those, decode only those, then chunked Jacobi-fixpoint NMS. Outer "round"
// loop selects the next key-order segment iff 200 kept not reached (exactness).

#define BATCH    8
#define NPRI     4096
#define TOPK     200
#define BLK      1024
#define CHUNK    512
#define NWORD    16       // CHUNK/32
#define HWORD    8
#define SELCAP   1024
#define SELMIN   897
#define CONF_TH  0.01f
#define NMS_TH   0.45f

typedef unsigned long long u64;

// ---------------- dynamic smem layout ----------------
#define OFF_SELBOX  0                          // float4[1024] 16384
#define OFF_ABOX    (OFF_SELBOX + 16384)       // float4[512]   8192
#define OFF_KBOX    (OFF_ABOX   + 8192)        // float4[200]   3200
#define OFF_SKEY    (OFF_KBOX   + 3200)        // u64[4096]    32768
#define OFF_SSEL    (OFF_SKEY   + 32768)       // u64[1024]     8192
#define OFF_SELAREA (OFF_SSEL   + 8192)        // float[1024]   4096
#define OFF_AAREA   (OFF_SELAREA+ 4096)        // float[512]    2048
#define OFF_ASCORE  (OFF_AAREA  + 2048)        // float[512]    2048
#define OFF_KAREA   (OFF_ASCORE + 2048)        // float[200]     800
#define OFF_HIST    (OFF_KAREA  + 800)         // int[8*256]    8192
#define OFF_SSUF    (OFF_HIST   + 8192)        // int[256]      1024
#define SMEM_BYTES  (OFF_SSUF   + 1024)

// compare-exchange: a is the LOWER-index element. desc=true -> a gets the max.
__device__ __forceinline__ void ce(u64 &a, u64 &b, bool desc) {
    u64 lo = a < b ? a : b;
    u64 hi = a < b ? b : a;
    a = desc ? hi : lo;
    b = desc ? lo : hi;
}

__device__ __forceinline__ void local_merge4(u64 v[4], bool d) {
    ce(v[0],v[2],d); ce(v[1],v[3],d);
    ce(v[0],v[1],d); ce(v[2],v[3],d);
}

__device__ __forceinline__ void local_sort4(u64 v[4], bool dir4) {
    ce(v[0],v[1],true);  ce(v[2],v[3],false);
    ce(v[0],v[2],dir4);  ce(v[1],v[3],dir4);
    ce(v[0],v[1],dir4);  ce(v[2],v[3],dir4);
}

__device__ __forceinline__ void shfl_stage4(u64 v[4], int d, bool dirT, int tid) {
    bool keep_max = (((tid & d) == 0) == dirT);
    #pragma unroll
    for (int r = 0; r < 4; r++) {
        u64 o = __shfl_xor_sync(0xffffffffu, v[r], d);
        v[r] = keep_max ? (v[r] > o ? v[r] : o) : (v[r] < o ? v[r] : o);
    }
}

__global__ __launch_bounds__(BLK, 1)
void post_rois_kernel(const float* __restrict__ loc,
                      const float* __restrict__ conf,
                      const float* __restrict__ prior,
                      float* __restrict__ out)
{
    const int b    = blockIdx.x;
    const int tid  = threadIdx.x;
    const int wid  = tid >> 5;
    const int lane = tid & 31;

    extern __shared__ unsigned char smem_raw[];
    float4*   selbox  = (float4*)(smem_raw + OFF_SELBOX);
    float4*   abox    = (float4*)(smem_raw + OFF_ABOX);
    float4*   kbox    = (float4*)(smem_raw + OFF_KBOX);
    u64*      skey    = (u64*)   (smem_raw + OFF_SKEY);
    u64*      ssel    = (u64*)   (smem_raw + OFF_SSEL);
    float*    selarea = (float*) (smem_raw + OFF_SELAREA);
    float*    aarea   = (float*) (smem_raw + OFF_AAREA);
    float*    ascore  = (float*) (smem_raw + OFF_ASCORE);
    float*    karea   = (float*) (smem_raw + OFF_KAREA);
    int*      hist8   = (int*)   (smem_raw + OFF_HIST);
    int*      Ssuf    = (int*)   (smem_raw + OFF_SSUF);

    __shared__ int wcnt[16], wbase[17];
    __shared__ unsigned supvec[NWORD];
    __shared__ unsigned char hsup[CHUNK];
    __shared__ unsigned char hns[CHUNK];
    __shared__ int skept, sScnt, sDone, sLast, sP, sCntAbove;
    __shared__ u64 sB, sPref;

    // ---- zero this image's output slice ----
    float* ob = out + (size_t)b * 2 * TOPK * 5;
    for (int i = tid; i < 2 * TOPK * 5; i += BLK) ob[i] = 0.0f;
    if (tid == 0) skept = 0;

    // ---- phase 1: softmax scores, pack into sortable u64 ----
    for (int n = tid; n < NPRI; n += BLK) {
        float c0 = conf[((size_t)b * NPRI + n) * 2 + 0];
        float c1 = conf[((size_t)b * NPRI + n) * 2 + 1];
        float m  = fmaxf(c0, c1);
        float e0 = expf(__fsub_rn(c0, m));
        float e1 = expf(__fsub_rn(c1, m));
        float s  = __fdiv_rn(e1, __fadd_rn(e0, e1));
        skey[n] = ((u64)__float_as_uint(s) << 32) | (unsigned)(NPRI - 1 - n);
    }
    __syncthreads();

    u64 ub = 0xFFFFFFFFFFFFFFFFull;   // exclusive upper bound for this round's keys

    // =========================== round loop ===========================
    while (true) {
        // ---- radix select: B such that P = #{B <= key < ub} in [SELMIN, SELCAP],
        //      or everything remaining if fewer (sLast) ----
        if (tid == 0) { sDone = 0; sLast = 0; sPref = 0; sCntAbove = 0; }
        __syncthreads();

        for (int shift = 56; shift >= 0; shift -= 8) {
            for (int h = tid; h < 8 * 256; h += BLK) hist8[h] = 0;
            __syncthreads();
            u64 pref = sPref;
            #pragma unroll
            for (int r = 0; r < 4; r++) {
                u64 key = skey[tid * 4 + r];
                if (key < ub && (shift == 56 || (key >> (shift + 8)) == pref))
                    atomicAdd(&hist8[((wid & 7) << 8) | (int)((key >> shift) & 255)], 1);
            }
            __syncthreads();
            if (tid < 256) {
                int s0 = 0;
                #pragma unroll
                for (int q = 0; q < 8; q++) s0 += hist8[(q << 8) | tid];
                Ssuf[tid] = s0;
            }
            __syncthreads();
            if (tid < 32) {
                // lane owns bins [8*lane, 8*lane+8); suffix sums S(b)=sum_{b'>=b}
                int v0[8];
                #pragma unroll
                for (int q = 0; q < 8; q++) v0[q] = Ssuf[(lane << 3) + q];
                #pragma unroll
                for (int q = 6; q >= 0; q--) v0[q] += v0[q + 1];
                int mytot = v0[0];
                int inc = mytot;
                #pragma unroll
                for (int d = 1; d < 32; d <<= 1) {
                    int o = __shfl_down_sync(0xffffffffu, inc, d);
                    if (lane + d < 32) inc += o;
                }
                int excl = inc - mytot;                 // sum over lanes > me (higher bins)
                int ca = sCntAbove;
                int best = 1 << 20;
                #pragma unroll
                for (int q = 0; q < 8; q++) {
                    int bb = (lane << 3) + q;
                    if (ca + v0[q] + excl <= SELCAP) best = min(best, bb);
                }
                #pragma unroll
                for (int d = 16; d >= 1; d >>= 1)
                    best = min(best, __shfl_xor_sync(0xffffffffu, best, d));
                // S(best) computed on owner lane, broadcast
                int sval = 0;
                if (best < 256) {
                    int idx = best & 7;
                    int myS = v0[0];
                    #pragma unroll
                    for (int q = 1; q < 8; q++) myS = (idx == q) ? v0[q] : myS;
                    myS += excl;
                    sval = __shfl_sync(0xffffffffu, myS, best >> 3);
                }
                if (lane == 0) {
                    int Pacc = ca + sval;
                    bool accept = (best < 256) &&
                                  ((Pacc >= SELMIN) || (shift == 56 && best == 0));
                    if (accept) {
                        sDone = 1;
                        sB = ((sPref << 8) | (u64)best) << shift;
                        sP = Pacc;
                        sLast = (shift == 56 && best == 0) ? 1 : 0;
                    } else {
                        int bdesc = (best < 256) ? best - 1 : 255;
                        sPref = (sPref << 8) | (u64)bdesc;
                        sCntAbove = ca + sval;
                    }
                }
            }
            __syncthreads();
            if (sDone) break;
        }

        // ---- compact selected keys into ssel (unordered; sort follows) ----
        if (tid == 0) sScnt = 0;
        ssel[tid] = 0;                         // pad with key 0 (score 0)
        __syncthreads();
        u64 B = sB;
        #pragma unroll
        for (int r = 0; r < 4; r++) {
            u64 key = skey[tid * 4 + r];
            if (key >= B && key < ub) {
                int pos = atomicAdd(&sScnt, 1);
                ssel[pos] = key;
            }
        }
        __syncthreads();

        // ---- bitonic sort 1024 (descending), 4 elems/thread on threads 0..255 ----
        u64 v[4];
        if (tid < 256) {
            #pragma unroll
            for (int r = 0; r < 4; r++) v[r] = ssel[tid * 4 + r];
            local_sort4(v, (tid & 1) == 0);
            for (int k = 8; k <= 128; k <<= 1) {
                bool dirT = ((tid & (k >> 2)) == 0);
                for (int d = (k >> 3); d >= 1; d >>= 1) shfl_stage4(v, d, dirT, tid);
                local_merge4(v, dirT);
            }
        }
        for (int k = 256; k <= SELCAP; k <<= 1) {
            if (tid < 256) {
                #pragma unroll
                for (int r = 0; r < 4; r++) ssel[tid * 4 + r] = v[r];
            }
            __syncthreads();
            for (int j = (k >> 1); j >= 128; j >>= 1) {
                if (tid < 512) {
                    int i = ((tid & ~(j - 1)) << 1) | (tid & (j - 1));
                    int p = i | j;
                    u64 a = ssel[i], c = ssel[p];
                    bool desc = ((i & k) == 0);
                    if (desc ? (a < c) : (a > c)) { ssel[i] = c; ssel[p] = a; }
                }
                __syncthreads();
            }
            if (tid < 256) {
                #pragma unroll
                for (int r = 0; r < 4; r++) v[r] = ssel[tid * 4 + r];
                bool dirT = ((tid & (k >> 2)) == 0);
                for (int d = 16; d >= 1; d >>= 1) shfl_stage4(v, d, dirT, tid);
                local_merge4(v, dirT);
            }
        }
        if (tid < 256) {
            #pragma unroll
            for (int r = 0; r < 4; r++) ssel[tid * 4 + r] = v[r];
        }
        __syncthreads();

        // ---- decode selected boxes (pinned IEEE, no FMA); pads decode harmlessly ----
        {
            int p = tid;                                   // BLK == SELCAP
            int n = NPRI - 1 - (int)(unsigned)(ssel[p] & 0xffffffffu);
            const float* lp = loc + ((size_t)b * NPRI + n) * 4;
            float lx = lp[0], ly = lp[1], lw = lp[2], lh = lp[3];
            float pcx = prior[n * 4 + 0], pcy = prior[n * 4 + 1];
            float pw  = prior[n * 4 + 2], ph  = prior[n * 4 + 3];

            float cx = __fadd_rn(pcx, __fmul_rn(__fmul_rn(lx, 0.1f), pw));
            float cy = __fadd_rn(pcy, __fmul_rn(__fmul_rn(ly, 0.1f), ph));
            float w  = __fmul_rn(pw, expf(__fmul_rn(lw, 0.2f)));
            float h  = __fmul_rn(ph, expf(__fmul_rn(lh, 0.2f)));
            float hw = __fmul_rn(w, 0.5f);
            float hh = __fmul_rn(h, 0.5f);
            float x1 = __fsub_rn(cx, hw), y1 = __fsub_rn(cy, hh);
            float x2 = __fadd_rn(cx, hw), y2 = __fadd_rn(cy, hh);

            selbox[p]  = make_float4(x1, y1, x2, y2);
            selarea[p] = __fmul_rn(__fsub_rn(x2, x1), __fsub_rn(y2, y1));
        }
        __syncthreads();

        // ---- chunked NMS, 2 threads/candidate, Jacobi fixpoint (exact greedy) ----
        const bool primary = tid < CHUNK;
        const int  ci      = tid & (CHUNK - 1);

        for (int c0 = 0; c0 < SELCAP; c0 += CHUNK) {
            if (skept >= TOPK) break;
            float topS = __uint_as_float((unsigned)(ssel[c0] >> 32));
            if (!(topS > CONF_TH)) break;

            // step 1: candidate vs already-kept boxes (split even/odd k)
            int   gi = c0 + ci;
            float s  = __uint_as_float((unsigned)(ssel[gi] >> 32));
            bool  okp = (s > CONF_TH);
            float4 bi = selbox[gi];
            float  ai = selarea[gi];

            int K = skept;
            for (int k = (primary ? 0 : 1); k < K; k += 2) {
                if (okp) {
                    float4 bj = kbox[k];
                    float iw = fmaxf(__fsub_rn(fminf(bi.z, bj.z), fmaxf(bi.x, bj.x)), 0.0f);
                    float ih = fmaxf(__fsub_rn(fminf(bi.w, bj.w), fmaxf(bi.y, bj.y)), 0.0f);
                    float inter = __fmul_rn(iw, ih);
                    if (inter > 0.0f) {
                        float denom = __fsub_rn(__fadd_rn(karea[k], ai), inter);
                        if (__fdiv_rn(inter, denom) > NMS_TH) okp = false;
                    }
                }
            }
            if (!primary) hsup[ci] = okp ? 0 : 1;
            __syncthreads();
            bool ok = primary && okp && (hsup[ci] == 0);

            // order-preserving compaction of survivors (primaries: warps 0..15)
            unsigned bal = __ballot_sync(0xffffffffu, ok);
            if (lane == 0 && wid < 16) wcnt[wid] = __popc(bal);
            __syncthreads();
            if (tid < 32) {                 // warp shfl-scan -> wbase
                int c = (lane < 16) ? wcnt[lane] : 0;
                #pragma unroll
                for (int d = 1; d < 16; d <<= 1) {
                    int o = __shfl_up_sync(0xffffffffu, c, d);
                    if (lane >= d) c += o;
                }
                if (lane < 16) wbase[lane + 1] = c;
                if (lane == 0) wbase[0] = 0;
            }
            if (tid < NWORD) supvec[tid] = 0;
            __syncthreads();
            int A = wbase[16];
            if (ok) {
                int pos = wbase[wid] + __popc(bal & ((1u << lane) - 1));
                abox[pos]   = bi;
                aarea[pos]  = ai;
                ascore[pos] = s;
            }
            __syncthreads();
            if (A == 0) continue;

            // step 2: suppressor half-mask in registers
            unsigned mT[HWORD];
            float4 bc = abox[ci < A ? ci : 0];
            float  ac = aarea[ci < A ? ci : 0];
            const int wlo = primary ? 0 : HWORD;
            #pragma unroll
            for (int w = 0; w < HWORD; w++) {
                unsigned bits = 0;
                int rbase = (wlo + w) << 5;
                if (ci < A && rbase < ci) {
                    int rend = ci - rbase; if (rend > 32) rend = 32;
                    for (int rr = 0; rr < rend; rr++) {
                        float4 br = abox[rbase + rr];
                        float iw = fmaxf(__fsub_rn(fminf(bc.z, br.z), fmaxf(bc.x, br.x)), 0.0f);
                        float ih = fmaxf(__fsub_rn(fminf(bc.w, br.w), fmaxf(bc.y, br.y)), 0.0f);
                        float inter = __fmul_rn(iw, ih);
                        if (inter > 0.0f) {
                            float denom = __fsub_rn(__fadd_rn(aarea[rbase + rr], ac), inter);
                            if (__fdiv_rn(inter, denom) > NMS_TH) bits |= (1u << rr);
                        }
                    }
                }
                mT[w] = bits;
            }

            // step 3: Jacobi fixpoint of sup_i = OR_{r<i} (!sup_r & mT_i[r])
            bool sup = false;
            for (int it = 0; it <= A; it++) {
                bool nsh = false;
                #pragma unroll
                for (int w = 0; w < HWORD; w++)
                    nsh |= (mT[w] & ~supvec[wlo + w]) != 0;
                if (!primary) hns[ci] = nsh ? 1 : 0;
                __syncthreads();

                bool changed = false;
                if (primary) {
                    bool ns = nsh || (hns[ci] != 0);
                    changed = (ns != sup);
                    sup = ns;
                }
                unsigned sb = __ballot_sync(0xffffffffu, sup);
                if (lane == 0 && wid < 16) supvec[wid] = sb;
                if (!__syncthreads_or(changed)) break;
            }

            // ordered compaction of kept, parallel output + kept-set append
            bool kept = primary && (ci < A) && !sup;
            unsigned kb = __ballot_sync(0xffffffffu, kept);
            if (lane == 0 && wid < 16) wcnt[wid] = __popc(kb);
            __syncthreads();
            if (tid < 32) {
                int c = (lane < 16) ? wcnt[lane] : 0;
                #pragma unroll
                for (int d = 1; d < 16; d <<= 1) {
                    int o = __shfl_up_sync(0xffffffffu, c, d);
                    if (lane >= d) c += o;
                }
                if (lane < 16) wbase[lane + 1] = c;
                if (lane == 0) wbase[0] = 0;
            }
            __syncthreads();
            int total = wbase[16];
            if (kept) {
                int pos = skept + wbase[wid] + __popc(kb & ((1u << lane) - 1));
                if (pos < TOPK) {
                    kbox[pos]  = bc;
                    karea[pos] = ac;
                    float* row = ob + (size_t)(TOPK + pos) * 5;
                    row[0] = ascore[ci];
                    row[1] = bc.x; row[2] = bc.y; row[3] = bc.z; row[4] = bc.w;
                }
            }
            __syncthreads();
            if (tid == 0) {
                int nk = skept + total;
                skept = nk < TOPK ? nk : TOPK;
            }
            __syncthreads();
        }

        // ---- round continuation (uniform): more valid keys below B? ----
        __syncthreads();
        float bscore = __uint_as_float((unsigned)(sB >> 32));
        bool more = (skept < TOPK) && (!sLast) && (bscore > CONF_TH);
        if (!more) break;
        ub = sB;
        __syncthreads();
    }
}

extern "C" void kernel_launch(void* const* d_in, const int* in_sizes, int n_in,
                              void* d_out, int out_size)
{
    const float* loc   = (const float*)d_in[0];
    const float* conf  = (const float*)d_in[1];
    const float* prior = (const float*)d_in[2];
    float* out = (float*)d_out;

    cudaFuncSetAttribute(post_rois_kernel,
                         cudaFuncAttributeMaxDynamicSharedMemorySize, SMEM_BYTES);
    post_rois_kernel<<<BATCH, BLK, SMEM_BYTES>>>(loc, conf, prior, out);
}

// round 14
// speedup vs baseline: 8.8771x; 1.8299x over previous
#include <cuda_runtime.h>
#include <math.h>

// Post_rois: SSD post-processing (softmax scores + box decode + greedy NMS + top-200)
// Inputs: loc [8,4096,4] f32, conf [8*4096,2] f32, prior [4096,4] f32 (cx,cy,w,h)
// Output: f32 [8, 2, 200, 5]; class-0 slice zeros, class-1 = NMS rows [s,x1,y1,x2,y2].
//
// Two kernels:
//  1) prep (wide grid): softmax->packed key + box decode for ALL priors -> global scratch
//  2) per-image (grid=8): radix-select exact top ~1024 keys, bitonic sort, gather boxes,
//     chunked Jacobi-fixpoint NMS (4 threads/candidate). Round loop guarantees exactness.

#define BATCH    8
#define NPRI     4096
#define TOPK     200
#define BLK      1024
#define CHUNK    256
#define HWORD    2        // words per thread-group (CHUNK/32/4)
#define SELCAP   1024
#define SELMIN   897
#define CONF_TH  0.01f
#define NMS_TH   0.45f

typedef unsigned long long u64;

// ---------------- global scratch (device globals: allocation-free) ----------------
__device__ u64    g_keys[BATCH * NPRI];
__device__ float4 g_box [BATCH * NPRI];
__device__ float  g_area[BATCH * NPRI];

// ---------------- dynamic smem layout (kernel 2) ----------------
#define OFF_SELBOX  0                          // float4[1024] 16384
#define OFF_ABOX    (OFF_SELBOX + 16384)       // float4[256]   4096
#define OFF_KBOX    (OFF_ABOX   + 4096)        // float4[200]   3200
#define OFF_SKEY    (OFF_KBOX   + 3200)        // u64[4096]    32768
#define OFF_SSEL    (OFF_SKEY   + 32768)       // u64[1024]     8192
#define OFF_SELAREA (OFF_SSEL   + 8192)        // float[1024]   4096
#define OFF_AAREA   (OFF_SELAREA+ 4096)        // float[256]    1024
#define OFF_ASCORE  (OFF_AAREA  + 1024)        // float[256]    1024
#define OFF_KAREA   (OFF_ASCORE + 1024)        // float[200]     800
#define OFF_HIST    (OFF_KAREA  + 800)         // int[8*256]    8192
#define OFF_SSUF    (OFF_HIST   + 8192)        // int[256]      1024
#define SMEM_BYTES  (OFF_SSUF   + 1024)

// ---------------- prep kernel: one prior per thread ----------------
#define P1BLK 512
__global__ __launch_bounds__(P1BLK)
void prep_kernel(const float* __restrict__ loc,
                 const float* __restrict__ conf,
                 const float* __restrict__ prior)
{
    int g = blockIdx.x * P1BLK + threadIdx.x;     // 0 .. BATCH*NPRI-1
    int n = g & (NPRI - 1);

    // softmax score -> packed sortable key (bit-identical to previous rounds)
    float c0 = conf[(size_t)g * 2 + 0];
    float c1 = conf[(size_t)g * 2 + 1];
    float m  = fmaxf(c0, c1);
    float e0 = expf(__fsub_rn(c0, m));
    float e1 = expf(__fsub_rn(c1, m));
    float s  = __fdiv_rn(e1, __fadd_rn(e0, e1));
    g_keys[g] = ((u64)__float_as_uint(s) << 32) | (unsigned)(NPRI - 1 - n);

    // box decode (pinned IEEE, no FMA)
    const float* lp = loc + (size_t)g * 4;
    float lx = lp[0], ly = lp[1], lw = lp[2], lh = lp[3];
    float pcx = prior[n * 4 + 0], pcy = prior[n * 4 + 1];
    float pw  = prior[n * 4 + 2], ph  = prior[n * 4 + 3];

    float cx = __fadd_rn(pcx, __fmul_rn(__fmul_rn(lx, 0.1f), pw));
    float cy = __fadd_rn(pcy, __fmul_rn(__fmul_rn(ly, 0.1f), ph));
    float w  = __fmul_rn(pw, expf(__fmul_rn(lw, 0.2f)));
    float h  = __fmul_rn(ph, expf(__fmul_rn(lh, 0.2f)));
    float hw = __fmul_rn(w, 0.5f);
    float hh = __fmul_rn(h, 0.5f);
    float x1 = __fsub_rn(cx, hw), y1 = __fsub_rn(cy, hh);
    float x2 = __fadd_rn(cx, hw), y2 = __fadd_rn(cy, hh);

    g_box[g]  = make_float4(x1, y1, x2, y2);
    g_area[g] = __fmul_rn(__fsub_rn(x2, x1), __fsub_rn(y2, y1));
}

// compare-exchange: a is the LOWER-index element. desc=true -> a gets the max.
__device__ __forceinline__ void ce(u64 &a, u64 &b, bool desc) {
    u64 lo = a < b ? a : b;
    u64 hi = a < b ? b : a;
    a = desc ? hi : lo;
    b = desc ? lo : hi;
}

__device__ __forceinline__ void local_merge4(u64 v[4], bool d) {
    ce(v[0],v[2],d); ce(v[1],v[3],d);
    ce(v[0],v[1],d); ce(v[2],v[3],d);
}

__device__ __forceinline__ void local_sort4(u64 v[4], bool dir4) {
    ce(v[0],v[1],true);  ce(v[2],v[3],false);
    ce(v[0],v[2],dir4);  ce(v[1],v[3],dir4);
    ce(v[0],v[1],dir4);  ce(v[2],v[3],dir4);
}

__device__ __forceinline__ void shfl_stage4(u64 v[4], int d, bool dirT, int tid) {
    bool keep_max = (((tid & d) == 0) == dirT);
    #pragma unroll
    for (int r = 0; r < 4; r++) {
        u64 o = __shfl_xor_sync(0xffffffffu, v[r], d);
        v[r] = keep_max ? (v[r] > o ? v[r] : o) : (v[r] < o ? v[r] : o);
    }
}

__global__ __launch_bounds__(BLK, 1)
void post_rois_kernel(float* __restrict__ out)
{
    const int b    = blockIdx.x;
    const int tid  = threadIdx.x;
    const int wid  = tid >> 5;
    const int lane = tid & 31;

    extern __shared__ unsigned char smem_raw[];
    float4*   selbox  = (float4*)(smem_raw + OFF_SELBOX);
    float4*   abox    = (float4*)(smem_raw + OFF_ABOX);
    float4*   kbox    = (float4*)(smem_raw + OFF_KBOX);
    u64*      skey    = (u64*)   (smem_raw + OFF_SKEY);
    u64*      ssel    = (u64*)   (smem_raw + OFF_SSEL);
    float*    selarea = (float*) (smem_raw + OFF_SELAREA);
    float*    aarea   = (float*) (smem_raw + OFF_AAREA);
    float*    ascore  = (float*) (smem_raw + OFF_ASCORE);
    float*    karea   = (float*) (smem_raw + OFF_KAREA);
    int*      hist8   = (int*)   (smem_raw + OFF_HIST);
    int*      Ssuf    = (int*)   (smem_raw + OFF_SSUF);

    __shared__ int wcnt[8], wbase[9];
    __shared__ unsigned supvec[8];
    __shared__ unsigned char hsupA[3 * CHUNK];
    __shared__ unsigned char hnsA[3 * CHUNK];
    __shared__ int skept, sScnt, sDone, sLast, sCntAbove;
    __shared__ u64 sB, sPref;

    // ---- zero this image's output slice; stage keys in smem ----
    float* ob = out + (size_t)b * 2 * TOPK * 5;
    for (int i = tid; i < 2 * TOPK * 5; i += BLK) ob[i] = 0.0f;
    if (tid == 0) skept = 0;
    #pragma unroll
    for (int r = 0; r < 4; r++)
        skey[tid * 4 + r] = g_keys[(size_t)b * NPRI + tid * 4 + r];
    __syncthreads();

    u64 ub = 0xFFFFFFFFFFFFFFFFull;

    // =========================== round loop ===========================
    while (true) {
        // ---- radix select: B s.t. P = #{B <= key < ub} in [SELMIN, SELCAP] ----
        if (tid == 0) { sDone = 0; sLast = 0; sPref = 0; sCntAbove = 0; }
        __syncthreads();

        for (int shift = 56; shift >= 0; shift -= 8) {
            for (int h = tid; h < 8 * 256; h += BLK) hist8[h] = 0;
            __syncthreads();
            u64 pref = sPref;
            #pragma unroll
            for (int r = 0; r < 4; r++) {
                u64 key = skey[tid * 4 + r];
                if (key < ub && (shift == 56 || (key >> (shift + 8)) == pref))
                    atomicAdd(&hist8[((wid & 7) << 8) | (int)((key >> shift) & 255)], 1);
            }
            __syncthreads();
            if (tid < 256) {
                int s0 = 0;
                #pragma unroll
                for (int q = 0; q < 8; q++) s0 += hist8[(q << 8) | tid];
                Ssuf[tid] = s0;
            }
            __syncthreads();
            if (tid < 32) {
                int v0[8];
                #pragma unroll
                for (int q = 0; q < 8; q++) v0[q] = Ssuf[(lane << 3) + q];
                #pragma unroll
                for (int q = 6; q >= 0; q--) v0[q] += v0[q + 1];
                int mytot = v0[0];
                int inc = mytot;
                #pragma unroll
                for (int d = 1; d < 32; d <<= 1) {
                    int o = __shfl_down_sync(0xffffffffu, inc, d);
                    if (lane + d < 32) inc += o;
                }
                int excl = inc - mytot;
                int ca = sCntAbove;
                int best = 1 << 20;
                #pragma unroll
                for (int q = 0; q < 8; q++) {
                    int bb = (lane << 3) + q;
                    if (ca + v0[q] + excl <= SELCAP) best = min(best, bb);
                }
                #pragma unroll
                for (int d = 16; d >= 1; d >>= 1)
                    best = min(best, __shfl_xor_sync(0xffffffffu, best, d));
                int sval = 0;
                if (best < 256) {
                    int idx = best & 7;
                    int myS = v0[0];
                    #pragma unroll
                    for (int q = 1; q < 8; q++) myS = (idx == q) ? v0[q] : myS;
                    myS += excl;
                    sval = __shfl_sync(0xffffffffu, myS, best >> 3);
                }
                if (lane == 0) {
                    int Pacc = ca + sval;
                    bool accept = (best < 256) &&
                                  ((Pacc >= SELMIN) || (shift == 56 && best == 0));
                    if (accept) {
                        sDone = 1;
                        sB = ((sPref << 8) | (u64)best) << shift;
                        sLast = (shift == 56 && best == 0) ? 1 : 0;
                    } else {
                        int bdesc = (best < 256) ? best - 1 : 255;
                        sPref = (sPref << 8) | (u64)bdesc;
                        sCntAbove = ca + sval;
                    }
                }
            }
            __syncthreads();
            if (sDone) break;
        }

        // ---- compact selected keys (unordered; sort follows) ----
        if (tid == 0) sScnt = 0;
        ssel[tid] = 0;
        __syncthreads();
        u64 B = sB;
        #pragma unroll
        for (int r = 0; r < 4; r++) {
            u64 key = skey[tid * 4 + r];
            if (key >= B && key < ub) {
                int pos = atomicAdd(&sScnt, 1);
                ssel[pos] = key;
            }
        }
        __syncthreads();

        // ---- bitonic sort 1024 (descending), 4 elems/thread on threads 0..255 ----
        u64 v[4];
        if (tid < 256) {
            #pragma unroll
            for (int r = 0; r < 4; r++) v[r] = ssel[tid * 4 + r];
            local_sort4(v, (tid & 1) == 0);
            for (int k = 8; k <= 128; k <<= 1) {
                bool dirT = ((tid & (k >> 2)) == 0);
                for (int d = (k >> 3); d >= 1; d >>= 1) shfl_stage4(v, d, dirT, tid);
                local_merge4(v, dirT);
            }
        }
        for (int k = 256; k <= SELCAP; k <<= 1) {
            if (tid < 256) {
                #pragma unroll
                for (int r = 0; r < 4; r++) ssel[tid * 4 + r] = v[r];
            }
            __syncthreads();
            for (int j = (k >> 1); j >= 128; j >>= 1) {
                if (tid < 512) {
                    int i = ((tid & ~(j - 1)) << 1) | (tid & (j - 1));
                    int p = i | j;
                    u64 a = ssel[i], c = ssel[p];
                    bool desc = ((i & k) == 0);
                    if (desc ? (a < c) : (a > c)) { ssel[i] = c; ssel[p] = a; }
                }
                __syncthreads();
            }
            if (tid < 256) {
                #pragma unroll
                for (int r = 0; r < 4; r++) v[r] = ssel[tid * 4 + r];
                bool dirT = ((tid & (k >> 2)) == 0);
                for (int d = 16; d >= 1; d >>= 1) shfl_stage4(v, d, dirT, tid);
                local_merge4(v, dirT);
            }
        }
        if (tid < 256) {
            #pragma unroll
            for (int r = 0; r < 4; r++) ssel[tid * 4 + r] = v[r];
        }
        __syncthreads();

        // ---- gather pre-decoded boxes for selected keys ----
        {
            int n = NPRI - 1 - (int)(unsigned)(ssel[tid] & 0xffffffffu);
            int gidx = b * NPRI + n;
            selbox[tid]  = g_box[gidx];
            selarea[tid] = g_area[gidx];
        }
        __syncthreads();

        // ---- chunked NMS, 4 threads/candidate, Jacobi fixpoint (exact greedy) ----
        const int grp = tid >> 8;                 // 0..3
        const int ci  = tid & (CHUNK - 1);
        const bool primary = (grp == 0);
        const int wlo = grp << 1;                 // this group's 2 mask words

        for (int c0 = 0; c0 < SELCAP; c0 += CHUNK) {
            if (skept >= TOPK) break;
            float topS = __uint_as_float((unsigned)(ssel[c0] >> 32));
            if (!(topS > CONF_TH)) break;

            // step 1: candidate vs already-kept boxes (k split 4 ways)
            int   gi = c0 + ci;
            float s  = __uint_as_float((unsigned)(ssel[gi] >> 32));
            bool  okp = (s > CONF_TH);
            float4 bi = selbox[gi];
            float  ai = selarea[gi];

            int K = skept;
            for (int k = grp; k < K; k += 4) {
                if (okp) {
                    float4 bj = kbox[k];
                    float iw = fmaxf(__fsub_rn(fminf(bi.z, bj.z), fmaxf(bi.x, bj.x)), 0.0f);
                    float ih = fmaxf(__fsub_rn(fminf(bi.w, bj.w), fmaxf(bi.y, bj.y)), 0.0f);
                    float inter = __fmul_rn(iw, ih);
                    if (inter > 0.0f) {
                        float denom = __fsub_rn(__fadd_rn(karea[k], ai), inter);
                        if (__fdiv_rn(inter, denom) > NMS_TH) okp = false;
                    }
                }
            }
            if (!primary) hsupA[((grp - 1) << 8) + ci] = okp ? 0 : 1;
            __syncthreads();
            bool ok = primary && okp && !hsupA[ci] && !hsupA[CHUNK + ci] && !hsupA[2 * CHUNK + ci];

            // order-preserving compaction of survivors (primaries: warps 0..7)
            unsigned bal = __ballot_sync(0xffffffffu, ok);
            if (lane == 0 && wid < 8) wcnt[wid] = __popc(bal);
            __syncthreads();
            if (tid < 32) {
                int c = (lane < 8) ? wcnt[lane] : 0;
                #pragma unroll
                for (int d = 1; d < 8; d <<= 1) {
                    int o = __shfl_up_sync(0xffffffffu, c, d);
                    if (lane >= d) c += o;
                }
                if (lane < 8) wbase[lane + 1] = c;
                if (lane == 0) wbase[0] = 0;
            }
            if (tid < 8) supvec[tid] = 0;
            __syncthreads();
            int A = wbase[8];
            if (ok) {
                int pos = wbase[wid] + __popc(bal & ((1u << lane) - 1));
                abox[pos]   = bi;
                aarea[pos]  = ai;
                ascore[pos] = s;
            }
            __syncthreads();
            if (A == 0) continue;

            // step 2: suppressor mask words [wlo, wlo+1] for candidate ci
            unsigned mT[HWORD];
            float4 bc = abox[ci < A ? ci : 0];
            float  ac = aarea[ci < A ? ci : 0];
            #pragma unroll
            for (int w = 0; w < HWORD; w++) {
                unsigned bits = 0;
                int rbase = (wlo + w) << 5;
                if (ci < A && rbase < ci) {
                    int rend = ci - rbase; if (rend > 32) rend = 32;
                    for (int rr = 0; rr < rend; rr++) {
                        float4 br = abox[rbase + rr];
                        float iw = fmaxf(__fsub_rn(fminf(bc.z, br.z), fmaxf(bc.x, br.x)), 0.0f);
                        float ih = fmaxf(__fsub_rn(fminf(bc.w, br.w), fmaxf(bc.y, br.y)), 0.0f);
                        float inter = __fmul_rn(iw, ih);
                        if (inter > 0.0f) {
                            float denom = __fsub_rn(__fadd_rn(aarea[rbase + rr], ac), inter);
                            if (__fdiv_rn(inter, denom) > NMS_TH) bits |= (1u << rr);
                        }
                    }
                }
                mT[w] = bits;
            }

            // step 3: Jacobi fixpoint of sup_i = OR_{r<i} (!sup_r & mask_i[r])
            bool sup = false;
            for (int it = 0; it <= A; it++) {
                bool nsh = ((mT[0] & ~supvec[wlo]) | (mT[1] & ~supvec[wlo + 1])) != 0;
                if (!primary) hnsA[((grp - 1) << 8) + ci] = nsh ? 1 : 0;
                __syncthreads();

                bool changed = false;
                if (primary) {
                    bool ns = nsh || hnsA[ci] || hnsA[CHUNK + ci] || hnsA[2 * CHUNK + ci];
                    changed = (ns != sup);
                    sup = ns;
                }
                unsigned sb = __ballot_sync(0xffffffffu, sup);
                if (lane == 0 && wid < 8) supvec[wid] = sb;
                if (!__syncthreads_or(changed)) break;
            }

            // ordered compaction of kept, parallel output + kept-set append
            bool kept = primary && (ci < A) && !sup;
            unsigned kb = __ballot_sync(0xffffffffu, kept);
            if (lane == 0 && wid < 8) wcnt[wid] = __popc(kb);
            __syncthreads();
            if (tid < 32) {
                int c = (lane < 8) ? wcnt[lane] : 0;
                #pragma unroll
                for (int d = 1; d < 8; d <<= 1) {
                    int o = __shfl_up_sync(0xffffffffu, c, d);
                    if (lane >= d) c += o;
                }
                if (lane < 8) wbase[lane + 1] = c;
                if (lane == 0) wbase[0] = 0;
            }
            __syncthreads();
            int total = wbase[8];
            if (kept) {
                int pos = skept + wbase[wid] + __popc(kb & ((1u << lane) - 1));
                if (pos < TOPK) {
                    kbox[pos]  = bc;
                    karea[pos] = ac;
                    float* row = ob + (size_t)(TOPK + pos) * 5;
                    row[0] = ascore[ci];
                    row[1] = bc.x; row[2] = bc.y; row[3] = bc.z; row[4] = bc.w;
                }
            }
            __syncthreads();
            if (tid == 0) {
                int nk = skept + total;
                skept = nk < TOPK ? nk : TOPK;
            }
            __syncthreads();
        }

        // ---- round continuation (uniform): more valid keys below B? ----
        __syncthreads();
        float bscore = __uint_as_float((unsigned)(sB >> 32));
        bool more = (skept < TOPK) && (!sLast) && (bscore > CONF_TH);
        if (!more) break;
        ub = sB;
        __syncthreads();
    }
}

extern "C" void kernel_launch(void* const* d_in, const int* in_sizes, int n_in,
                              void* d_out, int out_size)
{
    const float* loc   = (const float*)d_in[0];
    const float* conf  = (const float*)d_in[1];
    const float* prior = (const float*)d_in[2];
    float* out = (float*)d_out;

    prep_kernel<<<(BATCH * NPRI) / P1BLK, P1BLK>>>(loc, conf, prior);

    cudaFuncSetAttribute(post_rois_kernel,
                         cudaFuncAttributeMaxDynamicSharedMemorySize, SMEM_BYTES);
    post_rois_kernel<<<BATCH, BLK, SMEM_BYTES>>>(out);
}